// round 1
// baseline (speedup 1.0000x reference)
#include <cuda_runtime.h>
#include <math.h>

#define EMB 768
#define HEADS 12
#define HD 64
#define SEQ 4096
#define QKV_LD (3 * EMB)   // 2304

// Scratch (static device globals — no allocation)
__device__ float g_qkv[(size_t)SEQ * QKV_LD];   // [l][3*emb] : Q | K | V
__device__ float g_ctx[(size_t)SEQ * EMB];      // [l][h*64 + c]

// ---------------------------------------------------------------------------
// SGEMM: C[M,N] = A[M,K] @ B[N,K]^T (+ bias[N] if bias != nullptr)
// 128x128 block tile, BK=16, 256 threads, 8x8 microtile.
// Requires M%128==0, N%128==0, K%16==0 (true for all our shapes).
// ---------------------------------------------------------------------------
__global__ __launch_bounds__(256) void sgemm_abt(
    const float* __restrict__ A, const float* __restrict__ B,
    const float* __restrict__ bias, float* __restrict__ C,
    int M, int N, int K)
{
    __shared__ float As[16 * 132];
    __shared__ float Bs[16 * 132];

    const int tid = threadIdx.x;
    const int tx = tid & 15;        // 0..15 -> N
    const int ty = tid >> 4;        // 0..15 -> M
    const int bm0 = blockIdx.y * 128;
    const int bn0 = blockIdx.x * 128;

    float acc[8][8];
#pragma unroll
    for (int i = 0; i < 8; i++)
#pragma unroll
        for (int j = 0; j < 8; j++) acc[i][j] = 0.0f;

    for (int k0 = 0; k0 < K; k0 += 16) {
        // Load 128x16 tiles of A and B, transposed into [k][row] layout.
#pragma unroll
        for (int f = tid; f < 512; f += 256) {
            const int row = f >> 2;
            const int kq  = f & 3;
            float4 va = *(const float4*)(A + (size_t)(bm0 + row) * K + k0 + kq * 4);
            As[(kq * 4 + 0) * 132 + row] = va.x;
            As[(kq * 4 + 1) * 132 + row] = va.y;
            As[(kq * 4 + 2) * 132 + row] = va.z;
            As[(kq * 4 + 3) * 132 + row] = va.w;
            float4 vb = *(const float4*)(B + (size_t)(bn0 + row) * K + k0 + kq * 4);
            Bs[(kq * 4 + 0) * 132 + row] = vb.x;
            Bs[(kq * 4 + 1) * 132 + row] = vb.y;
            Bs[(kq * 4 + 2) * 132 + row] = vb.z;
            Bs[(kq * 4 + 3) * 132 + row] = vb.w;
        }
        __syncthreads();

#pragma unroll
        for (int kk = 0; kk < 16; kk++) {
            float a[8], b[8];
            *(float4*)&a[0] = *(const float4*)&As[kk * 132 + ty * 8];
            *(float4*)&a[4] = *(const float4*)&As[kk * 132 + ty * 8 + 4];
            *(float4*)&b[0] = *(const float4*)&Bs[kk * 132 + tx * 8];
            *(float4*)&b[4] = *(const float4*)&Bs[kk * 132 + tx * 8 + 4];
#pragma unroll
            for (int i = 0; i < 8; i++)
#pragma unroll
                for (int j = 0; j < 8; j++)
                    acc[i][j] = fmaf(a[i], b[j], acc[i][j]);
        }
        __syncthreads();
    }

    float bv[8];
#pragma unroll
    for (int j = 0; j < 8; j++)
        bv[j] = bias ? bias[bn0 + tx * 8 + j] : 0.0f;

#pragma unroll
    for (int i = 0; i < 8; i++) {
        float4 o0, o1;
        o0.x = acc[i][0] + bv[0]; o0.y = acc[i][1] + bv[1];
        o0.z = acc[i][2] + bv[2]; o0.w = acc[i][3] + bv[3];
        o1.x = acc[i][4] + bv[4]; o1.y = acc[i][5] + bv[5];
        o1.z = acc[i][6] + bv[6]; o1.w = acc[i][7] + bv[7];
        float* cp = C + (size_t)(bm0 + ty * 8 + i) * N + bn0 + tx * 8;
        *(float4*)cp       = o0;
        *(float4*)(cp + 4) = o1;
    }
}

// ---------------------------------------------------------------------------
// Flash attention, fp32. One block = (head, 128-query tile). 256 threads.
// Q tile resident in SMEM [d][q]; stream 64-key tiles (K tile [d][k],
// V tile [k][c]); online softmax; P staged in SMEM [k][q] for the PV GEMM.
// scores scaled by sqrt(64) = 8 (matches reference).
// ---------------------------------------------------------------------------
#define ATTN_SMEM_FLOATS (64 * 132 + 64 * 68 + 64 * 68 + 64 * 132)

__global__ __launch_bounds__(256) void attn_kernel(
    const float* __restrict__ qkv, float* __restrict__ ctx)
{
    extern __shared__ float sm[];
    float* Qs = sm;                       // [64 d][132]  (q-index inner)
    float* Ks = Qs + 64 * 132;            // [64 d][68]   (k-index inner)
    float* Vs = Ks + 64 * 68;             // [64 k][68]   (c-index inner)
    float* Ps = Vs + 64 * 68;             // [64 k][132]  (q-index inner)

    const int tid = threadIdx.x;
    const int tx = tid & 15;              // key/col group
    const int ty = tid >> 4;              // query/row group
    const int h  = blockIdx.y;
    const int q0 = blockIdx.x * 128;

    // Load Q tile (128 q x 64 d), transposed to [d][q].
#pragma unroll
    for (int f = tid; f < 128 * 16; f += 256) {
        const int q  = f >> 4;
        const int dq = f & 15;
        float4 v = *(const float4*)(qkv + (size_t)(q0 + q) * QKV_LD + h * HD + dq * 4);
        Qs[(dq * 4 + 0) * 132 + q] = v.x;
        Qs[(dq * 4 + 1) * 132 + q] = v.y;
        Qs[(dq * 4 + 2) * 132 + q] = v.z;
        Qs[(dq * 4 + 3) * 132 + q] = v.w;
    }

    float m[8], l[8], O[8][4];
#pragma unroll
    for (int i = 0; i < 8; i++) {
        m[i] = -1e30f;
        l[i] = 0.0f;
#pragma unroll
        for (int j = 0; j < 4; j++) O[i][j] = 0.0f;
    }

    for (int kt = 0; kt < SEQ; kt += 64) {
        __syncthreads();   // Q visible (1st iter); prev PV done (later iters)

        // Load K tile (transposed to [d][k]) and V tile ([k][c]).
#pragma unroll
        for (int f = tid; f < 64 * 16; f += 256) {
            const int k  = f >> 4;
            const int dq = f & 15;
            float4 kv = *(const float4*)(qkv + (size_t)(kt + k) * QKV_LD + EMB + h * HD + dq * 4);
            Ks[(dq * 4 + 0) * 68 + k] = kv.x;
            Ks[(dq * 4 + 1) * 68 + k] = kv.y;
            Ks[(dq * 4 + 2) * 68 + k] = kv.z;
            Ks[(dq * 4 + 3) * 68 + k] = kv.w;
            float4 vv = *(const float4*)(qkv + (size_t)(kt + k) * QKV_LD + 2 * EMB + h * HD + dq * 4);
            *(float4*)&Vs[k * 68 + dq * 4] = vv;
        }
        __syncthreads();

        // S = (Q K^T) * 8 : each thread 8 rows x 4 cols
        float s[8][4];
#pragma unroll
        for (int i = 0; i < 8; i++)
#pragma unroll
            for (int j = 0; j < 4; j++) s[i][j] = 0.0f;

#pragma unroll 16
        for (int d = 0; d < 64; d++) {
            float a[8], b[4];
            *(float4*)&a[0] = *(const float4*)&Qs[d * 132 + ty * 8];
            *(float4*)&a[4] = *(const float4*)&Qs[d * 132 + ty * 8 + 4];
            *(float4*)&b[0] = *(const float4*)&Ks[d * 68 + tx * 4];
#pragma unroll
            for (int i = 0; i < 8; i++)
#pragma unroll
                for (int j = 0; j < 4; j++)
                    s[i][j] = fmaf(a[i], b[j], s[i][j]);
        }

        // Online softmax: row reductions across the 16-thread tx group.
#pragma unroll
        for (int i = 0; i < 8; i++) {
            float rm = -1e30f;
#pragma unroll
            for (int j = 0; j < 4; j++) {
                s[i][j] *= 8.0f;
                rm = fmaxf(rm, s[i][j]);
            }
#pragma unroll
            for (int off = 1; off < 16; off <<= 1)
                rm = fmaxf(rm, __shfl_xor_sync(0xffffffffu, rm, off, 16));

            const float mn = fmaxf(m[i], rm);
            const float alpha = __expf(m[i] - mn);
            float p[4], rs = 0.0f;
#pragma unroll
            for (int j = 0; j < 4; j++) {
                p[j] = __expf(s[i][j] - mn);
                rs += p[j];
            }
#pragma unroll
            for (int off = 1; off < 16; off <<= 1)
                rs += __shfl_xor_sync(0xffffffffu, rs, off, 16);

            l[i] = l[i] * alpha + rs;
            m[i] = mn;
#pragma unroll
            for (int j = 0; j < 4; j++) O[i][j] *= alpha;
#pragma unroll
            for (int j = 0; j < 4; j++)
                Ps[(tx * 4 + j) * 132 + ty * 8 + i] = p[j];
        }
        __syncthreads();

        // O += P @ V
#pragma unroll 16
        for (int k = 0; k < 64; k++) {
            float a[8], b[4];
            *(float4*)&a[0] = *(const float4*)&Ps[k * 132 + ty * 8];
            *(float4*)&a[4] = *(const float4*)&Ps[k * 132 + ty * 8 + 4];
            *(float4*)&b[0] = *(const float4*)&Vs[k * 68 + tx * 4];
#pragma unroll
            for (int i = 0; i < 8; i++)
#pragma unroll
                for (int j = 0; j < 4; j++)
                    O[i][j] = fmaf(a[i], b[j], O[i][j]);
        }
    }

    // Normalize and write ctx[l][h*64 + c]
#pragma unroll
    for (int i = 0; i < 8; i++) {
        const float inv = 1.0f / l[i];
        float4 o;
        o.x = O[i][0] * inv; o.y = O[i][1] * inv;
        o.z = O[i][2] * inv; o.w = O[i][3] * inv;
        *(float4*)(ctx + (size_t)(q0 + ty * 8 + i) * EMB + h * HD + tx * 4) = o;
    }
}

// ---------------------------------------------------------------------------
extern "C" void kernel_launch(void* const* d_in, const int* in_sizes, int n_in,
                              void* d_out, int out_size)
{
    (void)in_sizes; (void)n_in; (void)out_size;
    const float* x     = (const float*)d_in[0];   // [1,4096,768]
    const float* qkv_w = (const float*)d_in[1];   // [2304,768]
    const float* out_w = (const float*)d_in[2];   // [768,768]
    const float* out_b = (const float*)d_in[3];   // [768]
    float* out = (float*)d_out;                   // [1,4096,768]

    float *qkv = nullptr, *ctx = nullptr;
    cudaGetSymbolAddress((void**)&qkv, g_qkv);
    cudaGetSymbolAddress((void**)&ctx, g_ctx);

    // 1) QKV projection: [4096,2304] = x @ qkv_w^T
    sgemm_abt<<<dim3(QKV_LD / 128, SEQ / 128), 256>>>(
        x, qkv_w, nullptr, qkv, SEQ, QKV_LD, EMB);

    // 2) Flash attention (12 heads x 32 query tiles)
    const size_t smem = ATTN_SMEM_FLOATS * sizeof(float);  // 100 KB
    cudaFuncSetAttribute(attn_kernel,
                         cudaFuncAttributeMaxDynamicSharedMemorySize, (int)smem);
    attn_kernel<<<dim3(SEQ / 128, HEADS), 256, smem>>>(qkv, ctx);

    // 3) Output projection + bias: [4096,768] = ctx @ out_w^T + out_b
    sgemm_abt<<<dim3(EMB / 128, SEQ / 128), 256>>>(
        ctx, out_w, out_b, out, SEQ, EMB, EMB);
}

// round 2
// speedup vs baseline: 1.1150x; 1.1150x over previous
#include <cuda_runtime.h>
#include <math.h>

#define EMB 768
#define HEADS 12
#define HD 64
#define SEQ 4096
#define QKV_LD (3 * EMB)   // 2304

// Scratch (static device globals — no allocation)
__device__ float g_qkv[(size_t)SEQ * QKV_LD];   // [l][3*emb] : Q | K | V
__device__ float g_ctx[(size_t)SEQ * EMB];      // [l][h*64 + c]

// ---------------------------------------------------------------------------
// Packed fp32x2 helpers (sm_103a FFMA2 path — full fp32 precision, 2 flops/issue)
// ---------------------------------------------------------------------------
typedef unsigned long long ull;

__device__ __forceinline__ ull dup2(float x) {
    ull r; asm("mov.b64 %0, {%1, %1};" : "=l"(r) : "f"(x)); return r;
}
__device__ __forceinline__ ull pack2(float x, float y) {
    ull r; asm("mov.b64 %0, {%1, %2};" : "=l"(r) : "f"(x), "f"(y)); return r;
}
__device__ __forceinline__ float2 unpack2(ull p) {
    float2 v; asm("mov.b64 {%0, %1}, %2;" : "=f"(v.x), "=f"(v.y) : "l"(p)); return v;
}
__device__ __forceinline__ void ffma2(ull& d, ull a, ull b) {
    asm("fma.rn.f32x2 %0, %1, %2, %0;" : "+l"(d) : "l"(a), "l"(b));
}
__device__ __forceinline__ void fmul2(ull& d, ull a, ull b) {
    asm("mul.rn.f32x2 %0, %1, %2;" : "=l"(d) : "l"(a), "l"(b));
}

// ---------------------------------------------------------------------------
// SGEMM: C[M,N] = A[M,K] @ B[N,K]^T (+ bias[N] if bias != nullptr)
// 128x128 block tile, BK=16, 256 threads, 8x8 microtile, FFMA2 inner loop.
// Accumulators packed along j (pairs of adjacent output columns).
// ---------------------------------------------------------------------------
__global__ __launch_bounds__(256) void sgemm_abt(
    const float* __restrict__ A, const float* __restrict__ B,
    const float* __restrict__ bias, float* __restrict__ C,
    int M, int N, int K)
{
    __shared__ __align__(16) float As[16 * 132];
    __shared__ __align__(16) float Bs[16 * 132];

    const int tid = threadIdx.x;
    const int tx = tid & 15;        // 0..15 -> N
    const int ty = tid >> 4;        // 0..15 -> M
    const int bm0 = blockIdx.y * 128;
    const int bn0 = blockIdx.x * 128;

    ull acc[8][4];                  // [i][jpair]: {C[i][2jp], C[i][2jp+1]}
#pragma unroll
    for (int i = 0; i < 8; i++)
#pragma unroll
        for (int jp = 0; jp < 4; jp++) acc[i][jp] = 0ull;

    for (int k0 = 0; k0 < K; k0 += 16) {
        // Load 128x16 tiles of A and B, transposed into [k][row] layout.
#pragma unroll
        for (int f = tid; f < 512; f += 256) {
            const int row = f >> 2;
            const int kq  = f & 3;
            float4 va = *(const float4*)(A + (size_t)(bm0 + row) * K + k0 + kq * 4);
            As[(kq * 4 + 0) * 132 + row] = va.x;
            As[(kq * 4 + 1) * 132 + row] = va.y;
            As[(kq * 4 + 2) * 132 + row] = va.z;
            As[(kq * 4 + 3) * 132 + row] = va.w;
            float4 vb = *(const float4*)(B + (size_t)(bn0 + row) * K + k0 + kq * 4);
            Bs[(kq * 4 + 0) * 132 + row] = vb.x;
            Bs[(kq * 4 + 1) * 132 + row] = vb.y;
            Bs[(kq * 4 + 2) * 132 + row] = vb.z;
            Bs[(kq * 4 + 3) * 132 + row] = vb.w;
        }
        __syncthreads();

#pragma unroll
        for (int kk = 0; kk < 16; kk++) {
            float a[8];
            *(float4*)&a[0] = *(const float4*)&As[kk * 132 + ty * 8];
            *(float4*)&a[4] = *(const float4*)&As[kk * 132 + ty * 8 + 4];
            ull bp[4];
            {
                ulonglong2 b0 = *(const ulonglong2*)&Bs[kk * 132 + tx * 8];
                ulonglong2 b1 = *(const ulonglong2*)&Bs[kk * 132 + tx * 8 + 4];
                bp[0] = b0.x; bp[1] = b0.y; bp[2] = b1.x; bp[3] = b1.y;
            }
#pragma unroll
            for (int i = 0; i < 8; i++) {
                const ull ad = dup2(a[i]);
#pragma unroll
                for (int jp = 0; jp < 4; jp++)
                    ffma2(acc[i][jp], ad, bp[jp]);
            }
        }
        __syncthreads();
    }

    float bv[8];
#pragma unroll
    for (int j = 0; j < 8; j++)
        bv[j] = bias ? bias[bn0 + tx * 8 + j] : 0.0f;

#pragma unroll
    for (int i = 0; i < 8; i++) {
        float c[8];
#pragma unroll
        for (int jp = 0; jp < 4; jp++) {
            float2 v = unpack2(acc[i][jp]);
            c[jp * 2 + 0] = v.x + bv[jp * 2 + 0];
            c[jp * 2 + 1] = v.y + bv[jp * 2 + 1];
        }
        float* cp = C + (size_t)(bm0 + ty * 8 + i) * N + bn0 + tx * 8;
        *(float4*)cp       = make_float4(c[0], c[1], c[2], c[3]);
        *(float4*)(cp + 4) = make_float4(c[4], c[5], c[6], c[7]);
    }
}

// ---------------------------------------------------------------------------
// Flash attention, fp32 with FFMA2. One block = (head, 128-query tile).
// 256 threads; thread tile 8 q-rows x 4 k-cols; accumulators packed along q.
// Score scale sqrt(64)=8 folded into the Q-tile load.
// ---------------------------------------------------------------------------
#define ATTN_SMEM_FLOATS (64 * 132 + 64 * 68 + 64 * 68 + 64 * 132)

__global__ __launch_bounds__(256) void attn_kernel(
    const float* __restrict__ qkv, float* __restrict__ ctx)
{
    extern __shared__ __align__(16) float sm[];
    float* Qs = sm;                       // [64 d][132]  (q inner), pre-scaled by 8
    float* Ks = Qs + 64 * 132;            // [64 d][68]   (k inner)
    float* Vs = Ks + 64 * 68;             // [64 k][68]   (c inner)
    float* Ps = Vs + 64 * 68;             // [64 k][132]  (q inner)

    const int tid = threadIdx.x;
    const int tx = tid & 15;              // key/col group
    const int ty = tid >> 4;              // query/row group
    const int h  = blockIdx.y;
    const int q0 = blockIdx.x * 128;

    // Load Q tile (128 q x 64 d), transposed to [d][q], scaled by 8.
#pragma unroll
    for (int f = tid; f < 128 * 16; f += 256) {
        const int q  = f >> 4;
        const int dq = f & 15;
        float4 v = *(const float4*)(qkv + (size_t)(q0 + q) * QKV_LD + h * HD + dq * 4);
        Qs[(dq * 4 + 0) * 132 + q] = v.x * 8.0f;
        Qs[(dq * 4 + 1) * 132 + q] = v.y * 8.0f;
        Qs[(dq * 4 + 2) * 132 + q] = v.z * 8.0f;
        Qs[(dq * 4 + 3) * 132 + q] = v.w * 8.0f;
    }

    float m[8], l[8];
    ull O[4][4];                          // [qpair][j]
#pragma unroll
    for (int i = 0; i < 8; i++) { m[i] = -1e30f; l[i] = 0.0f; }
#pragma unroll
    for (int p = 0; p < 4; p++)
#pragma unroll
        for (int j = 0; j < 4; j++) O[p][j] = 0ull;

    for (int kt = 0; kt < SEQ; kt += 64) {
        __syncthreads();   // Q visible (1st iter); prev PV done (later iters)

        // Load K tile (transposed to [d][k]) and V tile ([k][c]).
#pragma unroll
        for (int f = tid; f < 64 * 16; f += 256) {
            const int k  = f >> 4;
            const int dq = f & 15;
            float4 kv = *(const float4*)(qkv + (size_t)(kt + k) * QKV_LD + EMB + h * HD + dq * 4);
            Ks[(dq * 4 + 0) * 68 + k] = kv.x;
            Ks[(dq * 4 + 1) * 68 + k] = kv.y;
            Ks[(dq * 4 + 2) * 68 + k] = kv.z;
            Ks[(dq * 4 + 3) * 68 + k] = kv.w;
            float4 vv = *(const float4*)(qkv + (size_t)(kt + k) * QKV_LD + 2 * EMB + h * HD + dq * 4);
            *(float4*)&Vs[k * 68 + dq * 4] = vv;
        }
        __syncthreads();

        // S = Q K^T (already scaled): packed along q. s[p][j] = {S[2p][j],S[2p+1][j]}
        ull s[4][4];
#pragma unroll
        for (int p = 0; p < 4; p++)
#pragma unroll
            for (int j = 0; j < 4; j++) s[p][j] = 0ull;

#pragma unroll 16
        for (int d = 0; d < 64; d++) {
            ull ap[4];
            {
                ulonglong2 a0 = *(const ulonglong2*)&Qs[d * 132 + ty * 8];
                ulonglong2 a1 = *(const ulonglong2*)&Qs[d * 132 + ty * 8 + 4];
                ap[0] = a0.x; ap[1] = a0.y; ap[2] = a1.x; ap[3] = a1.y;
            }
            float b[4];
            *(float4*)&b[0] = *(const float4*)&Ks[d * 68 + tx * 4];
#pragma unroll
            for (int j = 0; j < 4; j++) {
                const ull bd = dup2(b[j]);
#pragma unroll
                for (int p = 0; p < 4; p++)
                    ffma2(s[p][j], ap[p], bd);
            }
        }

        // Unpack scores to rows
        float sf[8][4];
#pragma unroll
        for (int p = 0; p < 4; p++)
#pragma unroll
            for (int j = 0; j < 4; j++) {
                float2 v = unpack2(s[p][j]);
                sf[2 * p + 0][j] = v.x;
                sf[2 * p + 1][j] = v.y;
            }

        // Online softmax: row reductions across the 16-thread tx group.
        float pe[8][4], alpha[8];
#pragma unroll
        for (int i = 0; i < 8; i++) {
            float rm = fmaxf(fmaxf(sf[i][0], sf[i][1]), fmaxf(sf[i][2], sf[i][3]));
#pragma unroll
            for (int off = 1; off < 16; off <<= 1)
                rm = fmaxf(rm, __shfl_xor_sync(0xffffffffu, rm, off, 16));

            const float mn = fmaxf(m[i], rm);
            alpha[i] = __expf(m[i] - mn);
            float rs = 0.0f;
#pragma unroll
            for (int j = 0; j < 4; j++) {
                pe[i][j] = __expf(sf[i][j] - mn);
                rs += pe[i][j];
            }
#pragma unroll
            for (int off = 1; off < 16; off <<= 1)
                rs += __shfl_xor_sync(0xffffffffu, rs, off, 16);

            l[i] = l[i] * alpha[i] + rs;
            m[i] = mn;
        }

        // Scale O by alpha (packed along q)
#pragma unroll
        for (int p = 0; p < 4; p++) {
            const ull al = pack2(alpha[2 * p], alpha[2 * p + 1]);
#pragma unroll
            for (int j = 0; j < 4; j++)
                fmul2(O[p][j], O[p][j], al);
        }

        // Vectorized P store: Ps[k][q], q inner.
#pragma unroll
        for (int j = 0; j < 4; j++) {
            float* pp = &Ps[(tx * 4 + j) * 132 + ty * 8];
            *(float4*)pp       = make_float4(pe[0][j], pe[1][j], pe[2][j], pe[3][j]);
            *(float4*)(pp + 4) = make_float4(pe[4][j], pe[5][j], pe[6][j], pe[7][j]);
        }
        __syncthreads();

        // O += P @ V (packed along q)
#pragma unroll 16
        for (int k = 0; k < 64; k++) {
            ull ap[4];
            {
                ulonglong2 a0 = *(const ulonglong2*)&Ps[k * 132 + ty * 8];
                ulonglong2 a1 = *(const ulonglong2*)&Ps[k * 132 + ty * 8 + 4];
                ap[0] = a0.x; ap[1] = a0.y; ap[2] = a1.x; ap[3] = a1.y;
            }
            float b[4];
            *(float4*)&b[0] = *(const float4*)&Vs[k * 68 + tx * 4];
#pragma unroll
            for (int j = 0; j < 4; j++) {
                const ull bd = dup2(b[j]);
#pragma unroll
                for (int p = 0; p < 4; p++)
                    ffma2(O[p][j], ap[p], bd);
            }
        }
    }

    // Normalize and write ctx[l][h*64 + c]
#pragma unroll
    for (int p = 0; p < 4; p++) {
        const float inv0 = 1.0f / l[2 * p];
        const float inv1 = 1.0f / l[2 * p + 1];
        float r0[4], r1[4];
#pragma unroll
        for (int j = 0; j < 4; j++) {
            float2 v = unpack2(O[p][j]);
            r0[j] = v.x * inv0;
            r1[j] = v.y * inv1;
        }
        *(float4*)(ctx + (size_t)(q0 + ty * 8 + 2 * p) * EMB + h * HD + tx * 4) =
            make_float4(r0[0], r0[1], r0[2], r0[3]);
        *(float4*)(ctx + (size_t)(q0 + ty * 8 + 2 * p + 1) * EMB + h * HD + tx * 4) =
            make_float4(r1[0], r1[1], r1[2], r1[3]);
    }
}

// ---------------------------------------------------------------------------
extern "C" void kernel_launch(void* const* d_in, const int* in_sizes, int n_in,
                              void* d_out, int out_size)
{
    (void)in_sizes; (void)n_in; (void)out_size;
    const float* x     = (const float*)d_in[0];   // [1,4096,768]
    const float* qkv_w = (const float*)d_in[1];   // [2304,768]
    const float* out_w = (const float*)d_in[2];   // [768,768]
    const float* out_b = (const float*)d_in[3];   // [768]
    float* out = (float*)d_out;                   // [1,4096,768]

    float *qkv = nullptr, *ctx = nullptr;
    cudaGetSymbolAddress((void**)&qkv, g_qkv);
    cudaGetSymbolAddress((void**)&ctx, g_ctx);

    // 1) QKV projection: [4096,2304] = x @ qkv_w^T
    sgemm_abt<<<dim3(QKV_LD / 128, SEQ / 128), 256>>>(
        x, qkv_w, nullptr, qkv, SEQ, QKV_LD, EMB);

    // 2) Flash attention (12 heads x 32 query tiles)
    const size_t smem = ATTN_SMEM_FLOATS * sizeof(float);  // 100 KB
    cudaFuncSetAttribute(attn_kernel,
                         cudaFuncAttributeMaxDynamicSharedMemorySize, (int)smem);
    attn_kernel<<<dim3(SEQ / 128, HEADS), 256, smem>>>(qkv, ctx);

    // 3) Output projection + bias: [4096,768] = ctx @ out_w^T + out_b
    sgemm_abt<<<dim3(EMB / 128, SEQ / 128), 256>>>(
        ctx, out_w, out_b, out, SEQ, EMB, EMB);
}

// round 5
// speedup vs baseline: 1.1260x; 1.0098x over previous
#include <cuda_runtime.h>
#include <cuda_bf16.h>
#include <math.h>
#include <stdint.h>

#define EMB 768
#define HEADS 12
#define HD 64
#define SEQ 4096
#define QKV_LD (3 * EMB)   // 2304

// Scratch (static device globals — no allocation)
__device__ float g_qkv[(size_t)SEQ * QKV_LD];   // [l][3*emb] : Q | K | V
__device__ float g_ctx[(size_t)SEQ * EMB];      // [l][h*64 + c]

// ---------------------------------------------------------------------------
// Packed fp32x2 helpers (FFMA2 path — full fp32 precision)
// ---------------------------------------------------------------------------
typedef unsigned long long ull;

__device__ __forceinline__ ull dup2(float x) {
    ull r; asm("mov.b64 %0, {%1, %1};" : "=l"(r) : "f"(x)); return r;
}
__device__ __forceinline__ ull pack2(float x, float y) {
    ull r; asm("mov.b64 %0, {%1, %2};" : "=l"(r) : "f"(x), "f"(y)); return r;
}
__device__ __forceinline__ float2 unpack2(ull p) {
    float2 v; asm("mov.b64 {%0, %1}, %2;" : "=f"(v.x), "=f"(v.y) : "l"(p)); return v;
}
__device__ __forceinline__ void ffma2(ull& d, ull a, ull b) {
    asm("fma.rn.f32x2 %0, %1, %2, %0;" : "+l"(d) : "l"(a), "l"(b));
}
__device__ __forceinline__ void fmul2(ull& d, ull a, ull b) {
    asm("mul.rn.f32x2 %0, %1, %2;" : "=l"(d) : "l"(a), "l"(b));
}

// ---------------------------------------------------------------------------
// HMMA (mma.sync) bf16 helpers — supported on base sm_103 target.
// ---------------------------------------------------------------------------
__device__ __forceinline__ void mma_bf16(float* d, const uint32_t* a, const uint32_t* b) {
    asm volatile(
        "mma.sync.aligned.m16n8k16.row.col.f32.bf16.bf16.f32 "
        "{%0,%1,%2,%3}, {%4,%5,%6,%7}, {%8,%9}, {%0,%1,%2,%3};"
        : "+f"(d[0]), "+f"(d[1]), "+f"(d[2]), "+f"(d[3])
        : "r"(a[0]), "r"(a[1]), "r"(a[2]), "r"(a[3]), "r"(b[0]), "r"(b[1]));
}

// fp32 -> bf16 limb split for a pair of floats; returns packed bf16x2 words.
__device__ __forceinline__ void split_pair(
    float x, float y, uint32_t& h, uint32_t& m, uint32_t& l, bool want3)
{
    __nv_bfloat162 hb = __float22bfloat162_rn(make_float2(x, y));
    float2 hf = __bfloat1622float2(hb);
    float rx = x - hf.x, ry = y - hf.y;
    __nv_bfloat162 mb = __float22bfloat162_rn(make_float2(rx, ry));
    h = *(uint32_t*)&hb;
    m = *(uint32_t*)&mb;
    if (want3) {
        float2 mf = __bfloat1622float2(mb);
        __nv_bfloat162 lb = __float22bfloat162_rn(make_float2(rx - mf.x, ry - mf.y));
        l = *(uint32_t*)&lb;
    } else {
        l = 0;
    }
}

// ---------------------------------------------------------------------------
// HMMA GEMM: C[M,N] = A[M,K] @ B[N,K]^T (+bias), fp32 via bf16 limb split.
// NSPLIT=3: products hh,hm,mh,hl,lh,mm (err ~2^-26).
// NSPLIT=2: products hh,hm,mh (err ~2^-17).
// 128x128 block tile, BK=32, 256 threads (8 warps, 2x4 grid, warp tile 64x32).
// SMEM limb tiles: [row][k] bf16, row stride 40 (conflict-free fragment LDS).
// ---------------------------------------------------------------------------
#define LT (128 * 40)   // bf16 elements per limb tile

template<int NSPLIT>
__global__ __launch_bounds__(256) void hmma_gemm_abt(
    const float* __restrict__ A, const float* __restrict__ B,
    const float* __restrict__ bias, float* __restrict__ C,
    int M, int N, int K)
{
    extern __shared__ __align__(16) char smem[];
    __nv_bfloat16* As = (__nv_bfloat16*)smem;            // [NSPLIT][128][40]
    __nv_bfloat16* Bs = As + NSPLIT * LT;                // [NSPLIT][128][40]

    const int tid  = threadIdx.x;
    const int lane = tid & 31;
    const int wid  = tid >> 5;
    const int wm   = wid >> 2;          // 0..1
    const int wn   = wid & 3;           // 0..3
    const int grp  = lane >> 2;         // 0..7
    const int tg   = lane & 3;          // 0..3
    const int bm0  = blockIdx.y * 128;
    const int bn0  = blockIdx.x * 128;

    float d[4][4][4];
#pragma unroll
    for (int am = 0; am < 4; am++)
#pragma unroll
        for (int an = 0; an < 4; an++)
#pragma unroll
            for (int r = 0; r < 4; r++) d[am][an][r] = 0.0f;

    const int NPR = (NSPLIT == 3) ? 6 : 3;
    // First 3 products {hh,hm,mh} valid for NSPLIT=2; all 6 for NSPLIT=3.
    const int PA[6] = {0, 0, 1, 0, 2, 1};
    const int PB[6] = {0, 1, 0, 2, 0, 1};

    for (int k0 = 0; k0 < K; k0 += 32) {
        __syncthreads();   // previous chunk's fragment reads done
        // Fill A and B limb tiles (each thread: 2 groups of 8 floats per half).
#pragma unroll
        for (int half = 0; half < 2; half++) {
            const float* src = half ? (B + (size_t)bn0 * K) : (A + (size_t)bm0 * K);
            __nv_bfloat16* dst = half ? Bs : As;
#pragma unroll
            for (int it = 0; it < 2; it++) {
                const int f   = tid + it * 256;   // 0..511
                const int row = f >> 2;           // 0..127
                const int c8  = f & 3;            // 8-float group
                const float* p = src + (size_t)row * K + k0 + c8 * 8;
                float4 v0 = *(const float4*)p;
                float4 v1 = *(const float4*)(p + 4);
                uint32_t h[4], m[4], l[4];
                split_pair(v0.x, v0.y, h[0], m[0], l[0], NSPLIT == 3);
                split_pair(v0.z, v0.w, h[1], m[1], l[1], NSPLIT == 3);
                split_pair(v1.x, v1.y, h[2], m[2], l[2], NSPLIT == 3);
                split_pair(v1.z, v1.w, h[3], m[3], l[3], NSPLIT == 3);
                const int base = row * 40 + c8 * 8;
#pragma unroll
                for (int j = 0; j < 4; j++) {
                    *(uint32_t*)&dst[0 * LT + base + j * 2] = h[j];
                    *(uint32_t*)&dst[1 * LT + base + j * 2] = m[j];
                    if (NSPLIT == 3)
                        *(uint32_t*)&dst[2 * LT + base + j * 2] = l[j];
                }
            }
        }
        __syncthreads();

#pragma unroll
        for (int ks = 0; ks < 2; ks++) {
#pragma unroll
            for (int p = 0; p < NPR; p++) {
                const int la = PA[p], lb = PB[p];
                uint32_t afr[4][4];
#pragma unroll
                for (int am = 0; am < 4; am++) {
                    const __nv_bfloat16* ap =
                        As + la * LT + (wm * 64 + am * 16 + grp) * 40 + ks * 16 + tg * 2;
                    afr[am][0] = *(const uint32_t*)ap;
                    afr[am][1] = *(const uint32_t*)(ap + 8 * 40);
                    afr[am][2] = *(const uint32_t*)(ap + 8);
                    afr[am][3] = *(const uint32_t*)(ap + 8 * 40 + 8);
                }
#pragma unroll
                for (int an = 0; an < 4; an++) {
                    const __nv_bfloat16* bp =
                        Bs + lb * LT + (wn * 32 + an * 8 + grp) * 40 + ks * 16 + tg * 2;
                    uint32_t bfr[2];
                    bfr[0] = *(const uint32_t*)bp;
                    bfr[1] = *(const uint32_t*)(bp + 8);
#pragma unroll
                    for (int am = 0; am < 4; am++)
                        mma_bf16(d[am][an], afr[am], bfr);
                }
            }
        }
    }

    // Epilogue: fragment layout -> rows (grp, grp+8), cols (tg*2, tg*2+1).
#pragma unroll
    for (int am = 0; am < 4; am++) {
        const int r0 = bm0 + wm * 64 + am * 16 + grp;
#pragma unroll
        for (int an = 0; an < 4; an++) {
            const int c0 = bn0 + wn * 32 + an * 8 + tg * 2;
            float bv0 = 0.0f, bv1 = 0.0f;
            if (bias) { bv0 = bias[c0]; bv1 = bias[c0 + 1]; }
            *(float2*)&C[(size_t)r0 * N + c0] =
                make_float2(d[am][an][0] + bv0, d[am][an][1] + bv1);
            *(float2*)&C[(size_t)(r0 + 8) * N + c0] =
                make_float2(d[am][an][2] + bv0, d[am][an][3] + bv1);
        }
    }
}

// ---------------------------------------------------------------------------
// Flash attention, fp32 with FFMA2 + K/V register prefetch pipeline.
// One block = (head, 128-query tile), 256 threads, thread tile 8q x 4k.
// ---------------------------------------------------------------------------
#define ATTN_SMEM_FLOATS (64 * 132 + 64 * 68 + 64 * 68 + 64 * 132)

__global__ __launch_bounds__(256, 2) void attn_kernel(
    const float* __restrict__ qkv, float* __restrict__ ctx)
{
    extern __shared__ __align__(16) float sm[];
    float* Qs = sm;                       // [64 d][132]  (q inner), pre-scaled by 8
    float* Ks = Qs + 64 * 132;            // [64 d][68]   (k inner)
    float* Vs = Ks + 64 * 68;             // [64 k][68]   (c inner)
    float* Ps = Vs + 64 * 68;             // [64 k][132]  (q inner)

    const int tid = threadIdx.x;
    const int tx = tid & 15;              // key/col group
    const int ty = tid >> 4;              // query/row group
    const int h  = blockIdx.y;
    const int q0 = blockIdx.x * 128;

    // Per-thread K/V tile fragment coordinates (4 fragments).
    const int fk[4] = { (tid) >> 4, (tid + 256) >> 4, (tid + 512) >> 4, (tid + 768) >> 4 };
    const int fd = tid & 15;

    // Load Q tile (128 q x 64 d), transposed to [d][q], scaled by 8.
#pragma unroll
    for (int f = tid; f < 128 * 16; f += 256) {
        const int q  = f >> 4;
        const int dq = f & 15;
        float4 v = *(const float4*)(qkv + (size_t)(q0 + q) * QKV_LD + h * HD + dq * 4);
        Qs[(dq * 4 + 0) * 132 + q] = v.x * 8.0f;
        Qs[(dq * 4 + 1) * 132 + q] = v.y * 8.0f;
        Qs[(dq * 4 + 2) * 132 + q] = v.z * 8.0f;
        Qs[(dq * 4 + 3) * 132 + q] = v.w * 8.0f;
    }

    // Preload tile 0 K/V through registers and commit to SMEM.
    {
        float4 kr[4], vr[4];
#pragma unroll
        for (int i = 0; i < 4; i++) {
            kr[i] = *(const float4*)(qkv + (size_t)fk[i] * QKV_LD + EMB + h * HD + fd * 4);
            vr[i] = *(const float4*)(qkv + (size_t)fk[i] * QKV_LD + 2 * EMB + h * HD + fd * 4);
        }
#pragma unroll
        for (int i = 0; i < 4; i++) {
            Ks[(fd * 4 + 0) * 68 + fk[i]] = kr[i].x;
            Ks[(fd * 4 + 1) * 68 + fk[i]] = kr[i].y;
            Ks[(fd * 4 + 2) * 68 + fk[i]] = kr[i].z;
            Ks[(fd * 4 + 3) * 68 + fk[i]] = kr[i].w;
            *(float4*)&Vs[fk[i] * 68 + fd * 4] = vr[i];
        }
    }
    __syncthreads();

    float m[8], l[8];
    ull O[4][4];                          // [qpair][j]
#pragma unroll
    for (int i = 0; i < 8; i++) { m[i] = -1e30f; l[i] = 0.0f; }
#pragma unroll
    for (int p = 0; p < 4; p++)
#pragma unroll
        for (int j = 0; j < 4; j++) O[p][j] = 0ull;

    for (int kt = 0; kt < SEQ; kt += 64) {
        const bool pf = (kt + 64) < SEQ;

        // Prefetch next K tile into registers (latency hidden under S-GEMM).
        float4 kr[4];
        if (pf) {
#pragma unroll
            for (int i = 0; i < 4; i++)
                kr[i] = *(const float4*)(qkv + (size_t)(kt + 64 + fk[i]) * QKV_LD + EMB + h * HD + fd * 4);
        }

        // S = Q K^T (already scaled): packed along q.
        ull s[4][4];
#pragma unroll
        for (int p = 0; p < 4; p++)
#pragma unroll
            for (int j = 0; j < 4; j++) s[p][j] = 0ull;

#pragma unroll 16
        for (int d = 0; d < 64; d++) {
            ull ap[4];
            {
                ulonglong2 a0 = *(const ulonglong2*)&Qs[d * 132 + ty * 8];
                ulonglong2 a1 = *(const ulonglong2*)&Qs[d * 132 + ty * 8 + 4];
                ap[0] = a0.x; ap[1] = a0.y; ap[2] = a1.x; ap[3] = a1.y;
            }
            float b[4];
            *(float4*)&b[0] = *(const float4*)&Ks[d * 68 + tx * 4];
#pragma unroll
            for (int j = 0; j < 4; j++) {
                const ull bd = dup2(b[j]);
#pragma unroll
                for (int p = 0; p < 4; p++)
                    ffma2(s[p][j], ap[p], bd);
            }
        }

        // Prefetch next V tile (latency hidden under softmax + PV).
        float4 vr[4];
        if (pf) {
#pragma unroll
            for (int i = 0; i < 4; i++)
                vr[i] = *(const float4*)(qkv + (size_t)(kt + 64 + fk[i]) * QKV_LD + 2 * EMB + h * HD + fd * 4);
        }

        // Unpack scores to rows
        float sf[8][4];
#pragma unroll
        for (int p = 0; p < 4; p++)
#pragma unroll
            for (int j = 0; j < 4; j++) {
                float2 v = unpack2(s[p][j]);
                sf[2 * p + 0][j] = v.x;
                sf[2 * p + 1][j] = v.y;
            }

        // Online softmax across the 16-thread tx group.
        float pe[8][4], alpha[8];
#pragma unroll
        for (int i = 0; i < 8; i++) {
            float rm = fmaxf(fmaxf(sf[i][0], sf[i][1]), fmaxf(sf[i][2], sf[i][3]));
#pragma unroll
            for (int off = 1; off < 16; off <<= 1)
                rm = fmaxf(rm, __shfl_xor_sync(0xffffffffu, rm, off, 16));

            const float mn = fmaxf(m[i], rm);
            alpha[i] = __expf(m[i] - mn);
            float rs = 0.0f;
#pragma unroll
            for (int j = 0; j < 4; j++) {
                pe[i][j] = __expf(sf[i][j] - mn);
                rs += pe[i][j];
            }
#pragma unroll
            for (int off = 1; off < 16; off <<= 1)
                rs += __shfl_xor_sync(0xffffffffu, rs, off, 16);

            l[i] = l[i] * alpha[i] + rs;
            m[i] = mn;
        }

        // Scale O by alpha (packed along q)
#pragma unroll
        for (int p = 0; p < 4; p++) {
            const ull al = pack2(alpha[2 * p], alpha[2 * p + 1]);
#pragma unroll
            for (int j = 0; j < 4; j++)
                fmul2(O[p][j], O[p][j], al);
        }

        // Vectorized P store: Ps[k][q], q inner.
#pragma unroll
        for (int j = 0; j < 4; j++) {
            float* pp = &Ps[(tx * 4 + j) * 132 + ty * 8];
            *(float4*)pp       = make_float4(pe[0][j], pe[1][j], pe[2][j], pe[3][j]);
            *(float4*)(pp + 4) = make_float4(pe[4][j], pe[5][j], pe[6][j], pe[7][j]);
        }
        __syncthreads();   // sync1: Ps visible; all done reading Ks

        // Commit prefetched K for next iteration (Ks now free).
        if (pf) {
#pragma unroll
            for (int i = 0; i < 4; i++) {
                Ks[(fd * 4 + 0) * 68 + fk[i]] = kr[i].x;
                Ks[(fd * 4 + 1) * 68 + fk[i]] = kr[i].y;
                Ks[(fd * 4 + 2) * 68 + fk[i]] = kr[i].z;
                Ks[(fd * 4 + 3) * 68 + fk[i]] = kr[i].w;
            }
        }

        // O += P @ V (packed along q)
#pragma unroll 16
        for (int k = 0; k < 64; k++) {
            ull ap[4];
            {
                ulonglong2 a0 = *(const ulonglong2*)&Ps[k * 132 + ty * 8];
                ulonglong2 a1 = *(const ulonglong2*)&Ps[k * 132 + ty * 8 + 4];
                ap[0] = a0.x; ap[1] = a0.y; ap[2] = a1.x; ap[3] = a1.y;
            }
            float b[4];
            *(float4*)&b[0] = *(const float4*)&Vs[k * 68 + tx * 4];
#pragma unroll
            for (int j = 0; j < 4; j++) {
                const ull bd = dup2(b[j]);
#pragma unroll
                for (int p = 0; p < 4; p++)
                    ffma2(O[p][j], ap[p], bd);
            }
        }
        __syncthreads();   // sync2: all done reading Vs; Ks writes ordered

        // Commit prefetched V (next PV read is after next sync1).
        if (pf) {
#pragma unroll
            for (int i = 0; i < 4; i++)
                *(float4*)&Vs[fk[i] * 68 + fd * 4] = vr[i];
        }
    }

    // Normalize and write ctx[l][h*64 + c]
#pragma unroll
    for (int p = 0; p < 4; p++) {
        const float inv0 = 1.0f / l[2 * p];
        const float inv1 = 1.0f / l[2 * p + 1];
        float r0[4], r1[4];
#pragma unroll
        for (int j = 0; j < 4; j++) {
            float2 v = unpack2(O[p][j]);
            r0[j] = v.x * inv0;
            r1[j] = v.y * inv1;
        }
        *(float4*)(ctx + (size_t)(q0 + ty * 8 + 2 * p) * EMB + h * HD + tx * 4) =
            make_float4(r0[0], r0[1], r0[2], r0[3]);
        *(float4*)(ctx + (size_t)(q0 + ty * 8 + 2 * p + 1) * EMB + h * HD + tx * 4) =
            make_float4(r1[0], r1[1], r1[2], r1[3]);
    }
}

// ---------------------------------------------------------------------------
extern "C" void kernel_launch(void* const* d_in, const int* in_sizes, int n_in,
                              void* d_out, int out_size)
{
    (void)in_sizes; (void)n_in; (void)out_size;
    const float* x     = (const float*)d_in[0];   // [1,4096,768]
    const float* qkv_w = (const float*)d_in[1];   // [2304,768]
    const float* out_w = (const float*)d_in[2];   // [768,768]
    const float* out_b = (const float*)d_in[3];   // [768]
    float* out = (float*)d_out;                   // [1,4096,768]

    float *qkv = nullptr, *ctx = nullptr;
    cudaGetSymbolAddress((void**)&qkv, g_qkv);
    cudaGetSymbolAddress((void**)&ctx, g_ctx);

    // 1) QKV projection: [4096,2304] = x @ qkv_w^T   (HMMA bf16x3, 6 products)
    const int smem3 = 6 * LT * (int)sizeof(__nv_bfloat16);   // 61440 B
    cudaFuncSetAttribute(hmma_gemm_abt<3>,
                         cudaFuncAttributeMaxDynamicSharedMemorySize, smem3);
    hmma_gemm_abt<3><<<dim3(QKV_LD / 128, SEQ / 128), 256, smem3>>>(
        x, qkv_w, nullptr, qkv, SEQ, QKV_LD, EMB);

    // 2) Flash attention (12 heads x 32 query tiles)
    const size_t smem = ATTN_SMEM_FLOATS * sizeof(float);  // 100 KB
    cudaFuncSetAttribute(attn_kernel,
                         cudaFuncAttributeMaxDynamicSharedMemorySize, (int)smem);
    attn_kernel<<<dim3(SEQ / 128, HEADS), 256, smem>>>(qkv, ctx);

    // 3) Output projection + bias: [4096,768] = ctx @ out_w^T + out_b (bf16x2)
    const int smem2 = 4 * LT * (int)sizeof(__nv_bfloat16);   // 40960 B
    cudaFuncSetAttribute(hmma_gemm_abt<2>,
                         cudaFuncAttributeMaxDynamicSharedMemorySize, smem2);
    hmma_gemm_abt<2><<<dim3(EMB / 128, SEQ / 128), 256, smem2>>>(
        ctx, out_w, out_b, out, SEQ, EMB, EMB);
}

// round 7
// speedup vs baseline: 1.8106x; 1.6081x over previous
#include <cuda_runtime.h>
#include <cuda_bf16.h>
#include <cuda_fp16.h>
#include <math.h>
#include <stdint.h>

#define EMB 768
#define HEADS 12
#define HD 64
#define SEQ 4096
#define QKV_LD (3 * EMB)   // 2304

// Scratch (static device globals — no allocation)
__device__ __align__(16) float g_qkv[(size_t)SEQ * QKV_LD];  // [l][3*emb] : Q|K|V
__device__ __align__(16) float g_ctx[(size_t)SEQ * EMB];     // [l][h*64 + c]

// ---------------------------------------------------------------------------
// HMMA helpers (mma.sync — supported on base sm_103 target)
// ---------------------------------------------------------------------------
__device__ __forceinline__ void mma_bf16(float* d, const uint32_t* a, const uint32_t* b) {
    asm volatile(
        "mma.sync.aligned.m16n8k16.row.col.f32.bf16.bf16.f32 "
        "{%0,%1,%2,%3}, {%4,%5,%6,%7}, {%8,%9}, {%0,%1,%2,%3};"
        : "+f"(d[0]), "+f"(d[1]), "+f"(d[2]), "+f"(d[3])
        : "r"(a[0]), "r"(a[1]), "r"(a[2]), "r"(a[3]), "r"(b[0]), "r"(b[1]));
}
__device__ __forceinline__ void mma_f16(float* d, const uint32_t* a, const uint32_t* b) {
    asm volatile(
        "mma.sync.aligned.m16n8k16.row.col.f32.f16.f16.f32 "
        "{%0,%1,%2,%3}, {%4,%5,%6,%7}, {%8,%9}, {%0,%1,%2,%3};"
        : "+f"(d[0]), "+f"(d[1]), "+f"(d[2]), "+f"(d[3])
        : "r"(a[0]), "r"(a[1]), "r"(a[2]), "r"(a[3]), "r"(b[0]), "r"(b[1]));
}
__device__ __forceinline__ uint32_t h2bits(__half2 h) { return *(uint32_t*)&h; }

// fp32 pair -> fp16 hi/lo limbs (packed f16x2: x -> low half)
__device__ __forceinline__ void split_h2(float x, float y, uint32_t& hi, uint32_t& lo) {
    __half2 h = __floats2half2_rn(x, y);
    float2 f = __half22float2(h);
    __half2 l = __floats2half2_rn(x - f.x, y - f.y);
    hi = h2bits(h);
    lo = h2bits(l);
}

// fp32 pair -> bf16 limb split (for projection GEMMs)
__device__ __forceinline__ void split_pair_bf(
    float x, float y, uint32_t& h, uint32_t& m, uint32_t& l, bool want3)
{
    __nv_bfloat162 hb = __float22bfloat162_rn(make_float2(x, y));
    float2 hf = __bfloat1622float2(hb);
    float rx = x - hf.x, ry = y - hf.y;
    __nv_bfloat162 mb = __float22bfloat162_rn(make_float2(rx, ry));
    h = *(uint32_t*)&hb;
    m = *(uint32_t*)&mb;
    if (want3) {
        float2 mf = __bfloat1622float2(mb);
        __nv_bfloat162 lb = __float22bfloat162_rn(make_float2(rx - mf.x, ry - mf.y));
        l = *(uint32_t*)&lb;
    } else {
        l = 0;
    }
}

// ---------------------------------------------------------------------------
// HMMA GEMM: C[M,N] = A[M,K] @ B[N,K]^T (+bias), fp32 via bf16 limb split.
// (unchanged — passing at 271us)
// ---------------------------------------------------------------------------
#define LT (128 * 40)   // bf16 elements per limb tile

template<int NSPLIT>
__global__ __launch_bounds__(256) void hmma_gemm_abt(
    const float* __restrict__ A, const float* __restrict__ B,
    const float* __restrict__ bias, float* __restrict__ C,
    int M, int N, int K)
{
    extern __shared__ __align__(16) char smem[];
    __nv_bfloat16* As = (__nv_bfloat16*)smem;
    __nv_bfloat16* Bs = As + NSPLIT * LT;

    const int tid  = threadIdx.x;
    const int lane = tid & 31;
    const int wid  = tid >> 5;
    const int wm   = wid >> 2;
    const int wn   = wid & 3;
    const int grp  = lane >> 2;
    const int tg   = lane & 3;
    const int bm0  = blockIdx.y * 128;
    const int bn0  = blockIdx.x * 128;

    float d[4][4][4];
#pragma unroll
    for (int am = 0; am < 4; am++)
#pragma unroll
        for (int an = 0; an < 4; an++)
#pragma unroll
            for (int r = 0; r < 4; r++) d[am][an][r] = 0.0f;

    const int NPR = (NSPLIT == 3) ? 6 : 3;
    const int PA[6] = {0, 0, 1, 0, 2, 1};
    const int PB[6] = {0, 1, 0, 2, 0, 1};

    for (int k0 = 0; k0 < K; k0 += 32) {
        __syncthreads();
#pragma unroll
        for (int half = 0; half < 2; half++) {
            const float* src = half ? (B + (size_t)bn0 * K) : (A + (size_t)bm0 * K);
            __nv_bfloat16* dst = half ? Bs : As;
#pragma unroll
            for (int it = 0; it < 2; it++) {
                const int f   = tid + it * 256;
                const int row = f >> 2;
                const int c8  = f & 3;
                const float* p = src + (size_t)row * K + k0 + c8 * 8;
                float4 v0 = *(const float4*)p;
                float4 v1 = *(const float4*)(p + 4);
                uint32_t h[4], m[4], l[4];
                split_pair_bf(v0.x, v0.y, h[0], m[0], l[0], NSPLIT == 3);
                split_pair_bf(v0.z, v0.w, h[1], m[1], l[1], NSPLIT == 3);
                split_pair_bf(v1.x, v1.y, h[2], m[2], l[2], NSPLIT == 3);
                split_pair_bf(v1.z, v1.w, h[3], m[3], l[3], NSPLIT == 3);
                const int base = row * 40 + c8 * 8;
#pragma unroll
                for (int j = 0; j < 4; j++) {
                    *(uint32_t*)&dst[0 * LT + base + j * 2] = h[j];
                    *(uint32_t*)&dst[1 * LT + base + j * 2] = m[j];
                    if (NSPLIT == 3)
                        *(uint32_t*)&dst[2 * LT + base + j * 2] = l[j];
                }
            }
        }
        __syncthreads();

#pragma unroll
        for (int ks = 0; ks < 2; ks++) {
#pragma unroll
            for (int p = 0; p < NPR; p++) {
                const int la = PA[p], lb = PB[p];
                uint32_t afr[4][4];
#pragma unroll
                for (int am = 0; am < 4; am++) {
                    const __nv_bfloat16* ap =
                        As + la * LT + (wm * 64 + am * 16 + grp) * 40 + ks * 16 + tg * 2;
                    afr[am][0] = *(const uint32_t*)ap;
                    afr[am][1] = *(const uint32_t*)(ap + 8 * 40);
                    afr[am][2] = *(const uint32_t*)(ap + 8);
                    afr[am][3] = *(const uint32_t*)(ap + 8 * 40 + 8);
                }
#pragma unroll
                for (int an = 0; an < 4; an++) {
                    const __nv_bfloat16* bp =
                        Bs + lb * LT + (wn * 32 + an * 8 + grp) * 40 + ks * 16 + tg * 2;
                    uint32_t bfr[2];
                    bfr[0] = *(const uint32_t*)bp;
                    bfr[1] = *(const uint32_t*)(bp + 8);
#pragma unroll
                    for (int am = 0; am < 4; am++)
                        mma_bf16(d[am][an], afr[am], bfr);
                }
            }
        }
    }

#pragma unroll
    for (int am = 0; am < 4; am++) {
        const int r0 = bm0 + wm * 64 + am * 16 + grp;
#pragma unroll
        for (int an = 0; an < 4; an++) {
            const int c0 = bn0 + wn * 32 + an * 8 + tg * 2;
            float bv0 = 0.0f, bv1 = 0.0f;
            if (bias) { bv0 = bias[c0]; bv1 = bias[c0 + 1]; }
            *(float2*)&C[(size_t)r0 * N + c0] =
                make_float2(d[am][an][0] + bv0, d[am][an][1] + bv1);
            *(float2*)&C[(size_t)(r0 + 8) * N + c0] =
                make_float2(d[am][an][2] + bv0, d[am][an][3] + bv1);
        }
    }
}

// ---------------------------------------------------------------------------
// HMMA flash attention, fp16 limb split. Self-contained: K/V loaded fp32 from
// qkv, split in-kernel. P staged in SMEM (warp-private rows).
// Block = (128-q tile, head), 256 threads = 8 warps (warp w: q rows w*16+grp, +8).
// SMEM tiles stride 72 halves (conflict-free for fragment LDS and P STS).
// ---------------------------------------------------------------------------
#define SQH 0                    // Q hi  [128][72]
#define SQL (SQH + 128 * 72)     // Q lo
#define SKH (SQL + 128 * 72)     // K hi  [64 key][72 d]
#define SKL (SKH + 64 * 72)      // K lo
#define SVH (SKL + 64 * 72)      // V^T hi [64 c][72 k]
#define SVL (SVH + 64 * 72)      // V^T lo
#define SPH (SVL + 64 * 72)      // P hi  [128 q][72 k]
#define SPL (SPH + 128 * 72)     // P lo
#define ATTN_HALVES (SPL + 128 * 72)          // 55296
#define ATTN_SMEM_BYTES (ATTN_HALVES * 2)     // 110592

__global__ __launch_bounds__(256) void attn_hmma(
    const float* __restrict__ qkv, float* __restrict__ ctx)
{
    extern __shared__ __align__(16) __half sh[];
    const int tid  = threadIdx.x;
    const int lane = tid & 31;
    const int wid  = tid >> 5;
    const int grp  = lane >> 2;
    const int tg   = lane & 3;
    const int h    = blockIdx.y;
    const int q0   = blockIdx.x * 128;

    // Loader coords (round-3 proven): 4 key fragments per thread, 4-d chunk.
    const int fk[4] = { tid >> 4, (tid + 256) >> 4, (tid + 512) >> 4, (tid + 768) >> 4 };
    const int fd = tid & 15;

    // ---- Load Q tile, scale by 8, split into fp16 limbs ----
#pragma unroll
    for (int f = tid; f < 512; f += 256) {
        const int row = f >> 2, ch = f & 3;
        const float* p = qkv + (size_t)(q0 + row) * QKV_LD + h * HD + ch * 16;
        uint32_t hi[8], lo[8];
#pragma unroll
        for (int j = 0; j < 4; j++) {
            float4 v = *(const float4*)(p + j * 4);
            split_h2(v.x * 8.0f, v.y * 8.0f, hi[j * 2], lo[j * 2]);
            split_h2(v.z * 8.0f, v.w * 8.0f, hi[j * 2 + 1], lo[j * 2 + 1]);
        }
        const int o = row * 72 + ch * 16;
        *(uint4*)&sh[SQH + o]     = make_uint4(hi[0], hi[1], hi[2], hi[3]);
        *(uint4*)&sh[SQH + o + 8] = make_uint4(hi[4], hi[5], hi[6], hi[7]);
        *(uint4*)&sh[SQL + o]     = make_uint4(lo[0], lo[1], lo[2], lo[3]);
        *(uint4*)&sh[SQL + o + 8] = make_uint4(lo[4], lo[5], lo[6], lo[7]);
    }

    // K store: [key][d] limbs (8-byte stores)
    auto store_k = [&](int key, float4 v) {
        uint32_t h0, l0, h1, l1;
        split_h2(v.x, v.y, h0, l0);
        split_h2(v.z, v.w, h1, l1);
        const int o = key * 72 + fd * 4;
        *(uint2*)&sh[SKH + o] = make_uint2(h0, h1);
        *(uint2*)&sh[SKL + o] = make_uint2(l0, l1);
    };
    // V store transposed: [c][k] limbs (scalar half stores)
    auto store_v = [&](int key, float4 v) {
        float c4[4] = {v.x, v.y, v.z, v.w};
#pragma unroll
        for (int j = 0; j < 4; j++) {
            __half hh = __float2half_rn(c4[j]);
            sh[SVH + (fd * 4 + j) * 72 + key] = hh;
            sh[SVL + (fd * 4 + j) * 72 + key] = __float2half_rn(c4[j] - __half2float(hh));
        }
    };

    // ---- Preload tile 0 ----
#pragma unroll
    for (int i = 0; i < 4; i++) {
        float4 kv = *(const float4*)(qkv + (size_t)fk[i] * QKV_LD + EMB + h * HD + fd * 4);
        float4 vv = *(const float4*)(qkv + (size_t)fk[i] * QKV_LD + 2 * EMB + h * HD + fd * 4);
        store_k(fk[i], kv);
        store_v(fk[i], vv);
    }
    __syncthreads();

    float m0 = -1e30f, m1 = -1e30f, l0 = 0.0f, l1 = 0.0f;
    float O[8][4];
#pragma unroll
    for (int nt = 0; nt < 8; nt++)
#pragma unroll
        for (int r = 0; r < 4; r++) O[nt][r] = 0.0f;

    const int qrow = (wid * 16 + grp) * 72 + tg * 2;   // also the P-row base

    for (int kt = 0; kt < SEQ; kt += 64) {
        const bool pf = (kt + 64) < SEQ;

        // Prefetch next K tile fp32 (latency hidden under S-MMA)
        float4 kr[4];
        if (pf) {
#pragma unroll
            for (int i = 0; i < 4; i++)
                kr[i] = *(const float4*)(qkv + (size_t)(kt + 64 + fk[i]) * QKV_LD + EMB + h * HD + fd * 4);
        }

        // ---- S = Q K^T (3 fp16 limb products) ----
        float s[8][4];
#pragma unroll
        for (int nt = 0; nt < 8; nt++)
#pragma unroll
            for (int r = 0; r < 4; r++) s[nt][r] = 0.0f;

#pragma unroll
        for (int ks = 0; ks < 4; ks++) {
            const int qa = qrow + ks * 16;
            uint32_t ah[4], al[4];
            ah[0] = *(const uint32_t*)&sh[SQH + qa];
            ah[1] = *(const uint32_t*)&sh[SQH + qa + 8 * 72];
            ah[2] = *(const uint32_t*)&sh[SQH + qa + 8];
            ah[3] = *(const uint32_t*)&sh[SQH + qa + 8 * 72 + 8];
            al[0] = *(const uint32_t*)&sh[SQL + qa];
            al[1] = *(const uint32_t*)&sh[SQL + qa + 8 * 72];
            al[2] = *(const uint32_t*)&sh[SQL + qa + 8];
            al[3] = *(const uint32_t*)&sh[SQL + qa + 8 * 72 + 8];
#pragma unroll
            for (int nt = 0; nt < 8; nt++) {
                const int ka = (nt * 8 + grp) * 72 + ks * 16 + tg * 2;
                uint32_t kh[2], kl[2];
                kh[0] = *(const uint32_t*)&sh[SKH + ka];
                kh[1] = *(const uint32_t*)&sh[SKH + ka + 8];
                kl[0] = *(const uint32_t*)&sh[SKL + ka];
                kl[1] = *(const uint32_t*)&sh[SKL + ka + 8];
                mma_f16(s[nt], ah, kh);
                mma_f16(s[nt], al, kh);
                mma_f16(s[nt], ah, kl);
            }
        }

        // Prefetch next V tile fp32 (latency hidden under softmax + PV)
        float4 vr[4];
        if (pf) {
#pragma unroll
            for (int i = 0; i < 4; i++)
                vr[i] = *(const float4*)(qkv + (size_t)(kt + 64 + fk[i]) * QKV_LD + 2 * EMB + h * HD + fd * 4);
        }

        // ---- Online softmax (rows grp, grp+8; quad reduction) ----
        float mx0 = -1e30f, mx1 = -1e30f;
#pragma unroll
        for (int nt = 0; nt < 8; nt++) {
            mx0 = fmaxf(mx0, fmaxf(s[nt][0], s[nt][1]));
            mx1 = fmaxf(mx1, fmaxf(s[nt][2], s[nt][3]));
        }
        mx0 = fmaxf(mx0, __shfl_xor_sync(0xffffffffu, mx0, 1));
        mx0 = fmaxf(mx0, __shfl_xor_sync(0xffffffffu, mx0, 2));
        mx1 = fmaxf(mx1, __shfl_xor_sync(0xffffffffu, mx1, 1));
        mx1 = fmaxf(mx1, __shfl_xor_sync(0xffffffffu, mx1, 2));

        const float mn0 = fmaxf(m0, mx0), mn1 = fmaxf(m1, mx1);
        const float al0 = __expf(m0 - mn0), al1 = __expf(m1 - mn1);
        m0 = mn0; m1 = mn1;

        float sum0 = 0.0f, sum1 = 0.0f;
#pragma unroll
        for (int nt = 0; nt < 8; nt++) {
            s[nt][0] = __expf(s[nt][0] - mn0); sum0 += s[nt][0];
            s[nt][1] = __expf(s[nt][1] - mn0); sum0 += s[nt][1];
            s[nt][2] = __expf(s[nt][2] - mn1); sum1 += s[nt][2];
            s[nt][3] = __expf(s[nt][3] - mn1); sum1 += s[nt][3];
        }
        sum0 += __shfl_xor_sync(0xffffffffu, sum0, 1);
        sum0 += __shfl_xor_sync(0xffffffffu, sum0, 2);
        sum1 += __shfl_xor_sync(0xffffffffu, sum1, 1);
        sum1 += __shfl_xor_sync(0xffffffffu, sum1, 2);
        l0 = l0 * al0 + sum0;
        l1 = l1 * al1 + sum1;

#pragma unroll
        for (int nt = 0; nt < 8; nt++) {
            O[nt][0] *= al0; O[nt][1] *= al0;
            O[nt][2] *= al1; O[nt][3] *= al1;
        }

        // ---- P -> SMEM fp16 limbs [q][k] (warp-private rows) ----
#pragma unroll
        for (int nt = 0; nt < 8; nt++) {
            uint32_t hh, ll;
            const int pa0 = qrow + nt * 8;             // row grp (qrow includes tg*2)
            split_h2(s[nt][0], s[nt][1], hh, ll);
            *(uint32_t*)&sh[SPH + pa0] = hh;
            *(uint32_t*)&sh[SPL + pa0] = ll;
            split_h2(s[nt][2], s[nt][3], hh, ll);
            *(uint32_t*)&sh[SPH + pa0 + 8 * 72] = hh;
            *(uint32_t*)&sh[SPL + pa0 + 8 * 72] = ll;
        }
        __syncwarp(0xffffffffu);

        // ---- O += P V (3 fp16 limb products) ----
#pragma unroll
        for (int kc = 0; kc < 4; kc++) {
            const int pa = qrow + kc * 16;
            uint32_t ph[4], pl[4];
            ph[0] = *(const uint32_t*)&sh[SPH + pa];
            ph[1] = *(const uint32_t*)&sh[SPH + pa + 8 * 72];
            ph[2] = *(const uint32_t*)&sh[SPH + pa + 8];
            ph[3] = *(const uint32_t*)&sh[SPH + pa + 8 * 72 + 8];
            pl[0] = *(const uint32_t*)&sh[SPL + pa];
            pl[1] = *(const uint32_t*)&sh[SPL + pa + 8 * 72];
            pl[2] = *(const uint32_t*)&sh[SPL + pa + 8];
            pl[3] = *(const uint32_t*)&sh[SPL + pa + 8 * 72 + 8];
#pragma unroll
            for (int nt = 0; nt < 8; nt++) {
                const int va = (nt * 8 + grp) * 72 + kc * 16 + tg * 2;
                uint32_t vh[2], vl[2];
                vh[0] = *(const uint32_t*)&sh[SVH + va];
                vh[1] = *(const uint32_t*)&sh[SVH + va + 8];
                vl[0] = *(const uint32_t*)&sh[SVL + va];
                vl[1] = *(const uint32_t*)&sh[SVL + va + 8];
                mma_f16(O[nt], ph, vh);
                mma_f16(O[nt], pl, vh);
                mma_f16(O[nt], ph, vl);
            }
        }
        __syncthreads();   // all reads of K/V SMEM done

        // Commit prefetched K/V for next tile
        if (pf) {
#pragma unroll
            for (int i = 0; i < 4; i++) {
                store_k(fk[i], kr[i]);
                store_v(fk[i], vr[i]);
            }
        }
        __syncthreads();   // next K/V visible
    }

    // ---- Normalize and write ctx ----
    const float inv0 = 1.0f / l0, inv1 = 1.0f / l1;
    const int r0 = q0 + wid * 16 + grp;
#pragma unroll
    for (int nt = 0; nt < 8; nt++) {
        const int c = h * HD + nt * 8 + tg * 2;
        *(float2*)&ctx[(size_t)r0 * EMB + c] =
            make_float2(O[nt][0] * inv0, O[nt][1] * inv0);
        *(float2*)&ctx[(size_t)(r0 + 8) * EMB + c] =
            make_float2(O[nt][2] * inv1, O[nt][3] * inv1);
    }
}

// ---------------------------------------------------------------------------
extern "C" void kernel_launch(void* const* d_in, const int* in_sizes, int n_in,
                              void* d_out, int out_size)
{
    (void)in_sizes; (void)n_in; (void)out_size;
    const float* x     = (const float*)d_in[0];   // [1,4096,768]
    const float* qkv_w = (const float*)d_in[1];   // [2304,768]
    const float* out_w = (const float*)d_in[2];   // [768,768]
    const float* out_b = (const float*)d_in[3];   // [768]
    float* out = (float*)d_out;                   // [1,4096,768]

    float *qkv = nullptr, *ctx = nullptr;
    cudaGetSymbolAddress((void**)&qkv, g_qkv);
    cudaGetSymbolAddress((void**)&ctx, g_ctx);

    // 1) QKV projection (HMMA bf16x3)
    const int smem3 = 6 * LT * (int)sizeof(__nv_bfloat16);
    cudaFuncSetAttribute(hmma_gemm_abt<3>,
                         cudaFuncAttributeMaxDynamicSharedMemorySize, smem3);
    hmma_gemm_abt<3><<<dim3(QKV_LD / 128, SEQ / 128), 256, smem3>>>(
        x, qkv_w, nullptr, qkv, SEQ, QKV_LD, EMB);

    // 2) HMMA flash attention
    cudaFuncSetAttribute(attn_hmma,
                         cudaFuncAttributeMaxDynamicSharedMemorySize, ATTN_SMEM_BYTES);
    attn_hmma<<<dim3(SEQ / 128, HEADS), 256, ATTN_SMEM_BYTES>>>(qkv, ctx);

    // 3) Output projection + bias (HMMA bf16x2)
    const int smem2 = 4 * LT * (int)sizeof(__nv_bfloat16);
    cudaFuncSetAttribute(hmma_gemm_abt<2>,
                         cudaFuncAttributeMaxDynamicSharedMemorySize, smem2);
    hmma_gemm_abt<2><<<dim3(EMB / 128, SEQ / 128), 256, smem2>>>(
        ctx, out_w, out_b, out, SEQ, EMB, EMB);
}

// round 8
// speedup vs baseline: 1.8142x; 1.0020x over previous
#include <cuda_runtime.h>
#include <cuda_bf16.h>
#include <cuda_fp16.h>
#include <math.h>
#include <stdint.h>

#define EMB 768
#define HEADS 12
#define HD 64
#define SEQ 4096
#define QKV_LD (3 * EMB)   // 2304

// Scratch (static device globals — no allocation)
__device__ __align__(16) float g_qkv[(size_t)SEQ * QKV_LD];  // [l][3*emb] : Q|K|V
__device__ __align__(16) float g_ctx[(size_t)SEQ * EMB];     // [l][h*64 + c]

// ---------------------------------------------------------------------------
// HMMA helpers (mma.sync — supported on base sm_103 target)
// ---------------------------------------------------------------------------
__device__ __forceinline__ void mma_bf16(float* d, const uint32_t* a, const uint32_t* b) {
    asm volatile(
        "mma.sync.aligned.m16n8k16.row.col.f32.bf16.bf16.f32 "
        "{%0,%1,%2,%3}, {%4,%5,%6,%7}, {%8,%9}, {%0,%1,%2,%3};"
        : "+f"(d[0]), "+f"(d[1]), "+f"(d[2]), "+f"(d[3])
        : "r"(a[0]), "r"(a[1]), "r"(a[2]), "r"(a[3]), "r"(b[0]), "r"(b[1]));
}
__device__ __forceinline__ void mma_f16(float* d, const uint32_t* a, const uint32_t* b) {
    asm volatile(
        "mma.sync.aligned.m16n8k16.row.col.f32.f16.f16.f32 "
        "{%0,%1,%2,%3}, {%4,%5,%6,%7}, {%8,%9}, {%0,%1,%2,%3};"
        : "+f"(d[0]), "+f"(d[1]), "+f"(d[2]), "+f"(d[3])
        : "r"(a[0]), "r"(a[1]), "r"(a[2]), "r"(a[3]), "r"(b[0]), "r"(b[1]));
}
__device__ __forceinline__ uint32_t h2bits(__half2 h) { return *(uint32_t*)&h; }

// fp32 pair -> fp16 hi/lo limbs (packed f16x2: x -> low half)
__device__ __forceinline__ void split_h2(float x, float y, uint32_t& hi, uint32_t& lo) {
    __half2 h = __floats2half2_rn(x, y);
    float2 f = __half22float2(h);
    __half2 l = __floats2half2_rn(x - f.x, y - f.y);
    hi = h2bits(h);
    lo = h2bits(l);
}

// fp32 pair -> bf16 limb split (for projection GEMMs)
__device__ __forceinline__ void split_pair_bf(
    float x, float y, uint32_t& h, uint32_t& m, uint32_t& l, bool want3)
{
    __nv_bfloat162 hb = __float22bfloat162_rn(make_float2(x, y));
    float2 hf = __bfloat1622float2(hb);
    float rx = x - hf.x, ry = y - hf.y;
    __nv_bfloat162 mb = __float22bfloat162_rn(make_float2(rx, ry));
    h = *(uint32_t*)&hb;
    m = *(uint32_t*)&mb;
    if (want3) {
        float2 mf = __bfloat1622float2(mb);
        __nv_bfloat162 lb = __float22bfloat162_rn(make_float2(rx - mf.x, ry - mf.y));
        l = *(uint32_t*)&lb;
    } else {
        l = 0;
    }
}

// ---------------------------------------------------------------------------
// HMMA GEMM: C[M,N] = A[M,K] @ B[N,K]^T (+bias), fp32 via bf16 limb split.
// Now __launch_bounds__(256, 2): cap regs at 128 for 2 CTAs/SM.
// ---------------------------------------------------------------------------
#define LT (128 * 40)   // bf16 elements per limb tile

template<int NSPLIT>
__global__ __launch_bounds__(256, 2) void hmma_gemm_abt(
    const float* __restrict__ A, const float* __restrict__ B,
    const float* __restrict__ bias, float* __restrict__ C,
    int M, int N, int K)
{
    extern __shared__ __align__(16) char smem[];
    __nv_bfloat16* As = (__nv_bfloat16*)smem;
    __nv_bfloat16* Bs = As + NSPLIT * LT;

    const int tid  = threadIdx.x;
    const int lane = tid & 31;
    const int wid  = tid >> 5;
    const int wm   = wid >> 2;
    const int wn   = wid & 3;
    const int grp  = lane >> 2;
    const int tg   = lane & 3;
    const int bm0  = blockIdx.y * 128;
    const int bn0  = blockIdx.x * 128;

    float d[4][4][4];
#pragma unroll
    for (int am = 0; am < 4; am++)
#pragma unroll
        for (int an = 0; an < 4; an++)
#pragma unroll
            for (int r = 0; r < 4; r++) d[am][an][r] = 0.0f;

    const int NPR = (NSPLIT == 3) ? 6 : 3;
    const int PA[6] = {0, 0, 1, 0, 2, 1};
    const int PB[6] = {0, 1, 0, 2, 0, 1};

    for (int k0 = 0; k0 < K; k0 += 32) {
        __syncthreads();
#pragma unroll
        for (int half = 0; half < 2; half++) {
            const float* src = half ? (B + (size_t)bn0 * K) : (A + (size_t)bm0 * K);
            __nv_bfloat16* dst = half ? Bs : As;
#pragma unroll
            for (int it = 0; it < 2; it++) {
                const int f   = tid + it * 256;
                const int row = f >> 2;
                const int c8  = f & 3;
                const float* p = src + (size_t)row * K + k0 + c8 * 8;
                float4 v0 = *(const float4*)p;
                float4 v1 = *(const float4*)(p + 4);
                uint32_t h[4], m[4], l[4];
                split_pair_bf(v0.x, v0.y, h[0], m[0], l[0], NSPLIT == 3);
                split_pair_bf(v0.z, v0.w, h[1], m[1], l[1], NSPLIT == 3);
                split_pair_bf(v1.x, v1.y, h[2], m[2], l[2], NSPLIT == 3);
                split_pair_bf(v1.z, v1.w, h[3], m[3], l[3], NSPLIT == 3);
                const int base = row * 40 + c8 * 8;
#pragma unroll
                for (int j = 0; j < 4; j++) {
                    *(uint32_t*)&dst[0 * LT + base + j * 2] = h[j];
                    *(uint32_t*)&dst[1 * LT + base + j * 2] = m[j];
                    if (NSPLIT == 3)
                        *(uint32_t*)&dst[2 * LT + base + j * 2] = l[j];
                }
            }
        }
        __syncthreads();

#pragma unroll
        for (int ks = 0; ks < 2; ks++) {
#pragma unroll
            for (int p = 0; p < NPR; p++) {
                const int la = PA[p], lb = PB[p];
                uint32_t afr[4][4];
#pragma unroll
                for (int am = 0; am < 4; am++) {
                    const __nv_bfloat16* ap =
                        As + la * LT + (wm * 64 + am * 16 + grp) * 40 + ks * 16 + tg * 2;
                    afr[am][0] = *(const uint32_t*)ap;
                    afr[am][1] = *(const uint32_t*)(ap + 8 * 40);
                    afr[am][2] = *(const uint32_t*)(ap + 8);
                    afr[am][3] = *(const uint32_t*)(ap + 8 * 40 + 8);
                }
#pragma unroll
                for (int an = 0; an < 4; an++) {
                    const __nv_bfloat16* bp =
                        Bs + lb * LT + (wn * 32 + an * 8 + grp) * 40 + ks * 16 + tg * 2;
                    uint32_t bfr[2];
                    bfr[0] = *(const uint32_t*)bp;
                    bfr[1] = *(const uint32_t*)(bp + 8);
#pragma unroll
                    for (int am = 0; am < 4; am++)
                        mma_bf16(d[am][an], afr[am], bfr);
                }
            }
        }
    }

#pragma unroll
    for (int am = 0; am < 4; am++) {
        const int r0 = bm0 + wm * 64 + am * 16 + grp;
#pragma unroll
        for (int an = 0; an < 4; an++) {
            const int c0 = bn0 + wn * 32 + an * 8 + tg * 2;
            float bv0 = 0.0f, bv1 = 0.0f;
            if (bias) { bv0 = bias[c0]; bv1 = bias[c0 + 1]; }
            *(float2*)&C[(size_t)r0 * N + c0] =
                make_float2(d[am][an][0] + bv0, d[am][an][1] + bv1);
            *(float2*)&C[(size_t)(r0 + 8) * N + c0] =
                make_float2(d[am][an][2] + bv0, d[am][an][3] + bv1);
        }
    }
}

// ---------------------------------------------------------------------------
// HMMA flash attention, fp16 limb split. K/V loaded fp32 from qkv, split
// in-kernel. P staged in SMEM (warp-private rows).
// Now __launch_bounds__(256, 2): 110.6 KB smem x2 = 221 KB < 228 KB carveout,
// regs capped at 128 so two CTAs co-reside and softmax overlaps peer MMAs.
// ---------------------------------------------------------------------------
#define SQH 0                    // Q hi  [128][72]
#define SQL (SQH + 128 * 72)     // Q lo
#define SKH (SQL + 128 * 72)     // K hi  [64 key][72 d]
#define SKL (SKH + 64 * 72)      // K lo
#define SVH (SKL + 64 * 72)      // V^T hi [64 c][72 k]
#define SVL (SVH + 64 * 72)      // V^T lo
#define SPH (SVL + 64 * 72)      // P hi  [128 q][72 k]
#define SPL (SPH + 128 * 72)     // P lo
#define ATTN_HALVES (SPL + 128 * 72)          // 55296
#define ATTN_SMEM_BYTES (ATTN_HALVES * 2)     // 110592

__global__ __launch_bounds__(256, 2) void attn_hmma(
    const float* __restrict__ qkv, float* __restrict__ ctx)
{
    extern __shared__ __align__(16) __half sh[];
    const int tid  = threadIdx.x;
    const int lane = tid & 31;
    const int wid  = tid >> 5;
    const int grp  = lane >> 2;
    const int tg   = lane & 3;
    const int h    = blockIdx.y;
    const int q0   = blockIdx.x * 128;

    // Loader coords: 4 key fragments per thread, 4-d chunk.
    const int fk[4] = { tid >> 4, (tid + 256) >> 4, (tid + 512) >> 4, (tid + 768) >> 4 };
    const int fd = tid & 15;

    // ---- Load Q tile, scale by 8, split into fp16 limbs ----
#pragma unroll
    for (int f = tid; f < 512; f += 256) {
        const int row = f >> 2, ch = f & 3;
        const float* p = qkv + (size_t)(q0 + row) * QKV_LD + h * HD + ch * 16;
        uint32_t hi[8], lo[8];
#pragma unroll
        for (int j = 0; j < 4; j++) {
            float4 v = *(const float4*)(p + j * 4);
            split_h2(v.x * 8.0f, v.y * 8.0f, hi[j * 2], lo[j * 2]);
            split_h2(v.z * 8.0f, v.w * 8.0f, hi[j * 2 + 1], lo[j * 2 + 1]);
        }
        const int o = row * 72 + ch * 16;
        *(uint4*)&sh[SQH + o]     = make_uint4(hi[0], hi[1], hi[2], hi[3]);
        *(uint4*)&sh[SQH + o + 8] = make_uint4(hi[4], hi[5], hi[6], hi[7]);
        *(uint4*)&sh[SQL + o]     = make_uint4(lo[0], lo[1], lo[2], lo[3]);
        *(uint4*)&sh[SQL + o + 8] = make_uint4(lo[4], lo[5], lo[6], lo[7]);
    }

    // K store: [key][d] limbs (8-byte stores)
    auto store_k = [&](int key, float4 v) {
        uint32_t h0, l0, h1, l1;
        split_h2(v.x, v.y, h0, l0);
        split_h2(v.z, v.w, h1, l1);
        const int o = key * 72 + fd * 4;
        *(uint2*)&sh[SKH + o] = make_uint2(h0, h1);
        *(uint2*)&sh[SKL + o] = make_uint2(l0, l1);
    };
    // V store transposed: [c][k] limbs (scalar half stores)
    auto store_v = [&](int key, float4 v) {
        float c4[4] = {v.x, v.y, v.z, v.w};
#pragma unroll
        for (int j = 0; j < 4; j++) {
            __half hh = __float2half_rn(c4[j]);
            sh[SVH + (fd * 4 + j) * 72 + key] = hh;
            sh[SVL + (fd * 4 + j) * 72 + key] = __float2half_rn(c4[j] - __half2float(hh));
        }
    };

    // ---- Preload tile 0 ----
#pragma unroll
    for (int i = 0; i < 4; i++) {
        float4 kv = *(const float4*)(qkv + (size_t)fk[i] * QKV_LD + EMB + h * HD + fd * 4);
        float4 vv = *(const float4*)(qkv + (size_t)fk[i] * QKV_LD + 2 * EMB + h * HD + fd * 4);
        store_k(fk[i], kv);
        store_v(fk[i], vv);
    }
    __syncthreads();

    float m0 = -1e30f, m1 = -1e30f, l0 = 0.0f, l1 = 0.0f;
    float O[8][4];
#pragma unroll
    for (int nt = 0; nt < 8; nt++)
#pragma unroll
        for (int r = 0; r < 4; r++) O[nt][r] = 0.0f;

    const int qrow = (wid * 16 + grp) * 72 + tg * 2;   // also the P-row base

    for (int kt = 0; kt < SEQ; kt += 64) {
        const bool pf = (kt + 64) < SEQ;

        // Prefetch next K tile fp32 (latency hidden under S-MMA)
        float4 kr[4];
        if (pf) {
#pragma unroll
            for (int i = 0; i < 4; i++)
                kr[i] = *(const float4*)(qkv + (size_t)(kt + 64 + fk[i]) * QKV_LD + EMB + h * HD + fd * 4);
        }

        // ---- S = Q K^T (3 fp16 limb products) ----
        float s[8][4];
#pragma unroll
        for (int nt = 0; nt < 8; nt++)
#pragma unroll
            for (int r = 0; r < 4; r++) s[nt][r] = 0.0f;

#pragma unroll
        for (int ks = 0; ks < 4; ks++) {
            const int qa = qrow + ks * 16;
            uint32_t ah[4], al[4];
            ah[0] = *(const uint32_t*)&sh[SQH + qa];
            ah[1] = *(const uint32_t*)&sh[SQH + qa + 8 * 72];
            ah[2] = *(const uint32_t*)&sh[SQH + qa + 8];
            ah[3] = *(const uint32_t*)&sh[SQH + qa + 8 * 72 + 8];
            al[0] = *(const uint32_t*)&sh[SQL + qa];
            al[1] = *(const uint32_t*)&sh[SQL + qa + 8 * 72];
            al[2] = *(const uint32_t*)&sh[SQL + qa + 8];
            al[3] = *(const uint32_t*)&sh[SQL + qa + 8 * 72 + 8];
#pragma unroll
            for (int nt = 0; nt < 8; nt++) {
                const int ka = (nt * 8 + grp) * 72 + ks * 16 + tg * 2;
                uint32_t kh[2], kl[2];
                kh[0] = *(const uint32_t*)&sh[SKH + ka];
                kh[1] = *(const uint32_t*)&sh[SKH + ka + 8];
                kl[0] = *(const uint32_t*)&sh[SKL + ka];
                kl[1] = *(const uint32_t*)&sh[SKL + ka + 8];
                mma_f16(s[nt], ah, kh);
                mma_f16(s[nt], al, kh);
                mma_f16(s[nt], ah, kl);
            }
        }

        // Prefetch next V tile fp32 (latency hidden under softmax + PV)
        float4 vr[4];
        if (pf) {
#pragma unroll
            for (int i = 0; i < 4; i++)
                vr[i] = *(const float4*)(qkv + (size_t)(kt + 64 + fk[i]) * QKV_LD + 2 * EMB + h * HD + fd * 4);
        }

        // ---- Online softmax (rows grp, grp+8; quad reduction) ----
        float mx0 = -1e30f, mx1 = -1e30f;
#pragma unroll
        for (int nt = 0; nt < 8; nt++) {
            mx0 = fmaxf(mx0, fmaxf(s[nt][0], s[nt][1]));
            mx1 = fmaxf(mx1, fmaxf(s[nt][2], s[nt][3]));
        }
        mx0 = fmaxf(mx0, __shfl_xor_sync(0xffffffffu, mx0, 1));
        mx0 = fmaxf(mx0, __shfl_xor_sync(0xffffffffu, mx0, 2));
        mx1 = fmaxf(mx1, __shfl_xor_sync(0xffffffffu, mx1, 1));
        mx1 = fmaxf(mx1, __shfl_xor_sync(0xffffffffu, mx1, 2));

        const float mn0 = fmaxf(m0, mx0), mn1 = fmaxf(m1, mx1);
        const float al0 = __expf(m0 - mn0), al1 = __expf(m1 - mn1);
        m0 = mn0; m1 = mn1;

        float sum0 = 0.0f, sum1 = 0.0f;
#pragma unroll
        for (int nt = 0; nt < 8; nt++) {
            s[nt][0] = __expf(s[nt][0] - mn0); sum0 += s[nt][0];
            s[nt][1] = __expf(s[nt][1] - mn0); sum0 += s[nt][1];
            s[nt][2] = __expf(s[nt][2] - mn1); sum1 += s[nt][2];
            s[nt][3] = __expf(s[nt][3] - mn1); sum1 += s[nt][3];
        }
        sum0 += __shfl_xor_sync(0xffffffffu, sum0, 1);
        sum0 += __shfl_xor_sync(0xffffffffu, sum0, 2);
        sum1 += __shfl_xor_sync(0xffffffffu, sum1, 1);
        sum1 += __shfl_xor_sync(0xffffffffu, sum1, 2);
        l0 = l0 * al0 + sum0;
        l1 = l1 * al1 + sum1;

#pragma unroll
        for (int nt = 0; nt < 8; nt++) {
            O[nt][0] *= al0; O[nt][1] *= al0;
            O[nt][2] *= al1; O[nt][3] *= al1;
        }

        // ---- P -> SMEM fp16 limbs [q][k] (warp-private rows) ----
#pragma unroll
        for (int nt = 0; nt < 8; nt++) {
            uint32_t hh, ll;
            const int pa0 = qrow + nt * 8;
            split_h2(s[nt][0], s[nt][1], hh, ll);
            *(uint32_t*)&sh[SPH + pa0] = hh;
            *(uint32_t*)&sh[SPL + pa0] = ll;
            split_h2(s[nt][2], s[nt][3], hh, ll);
            *(uint32_t*)&sh[SPH + pa0 + 8 * 72] = hh;
            *(uint32_t*)&sh[SPL + pa0 + 8 * 72] = ll;
        }
        __syncwarp(0xffffffffu);

        // ---- O += P V (3 fp16 limb products) ----
#pragma unroll
        for (int kc = 0; kc < 4; kc++) {
            const int pa = qrow + kc * 16;
            uint32_t ph[4], pl[4];
            ph[0] = *(const uint32_t*)&sh[SPH + pa];
            ph[1] = *(const uint32_t*)&sh[SPH + pa + 8 * 72];
            ph[2] = *(const uint32_t*)&sh[SPH + pa + 8];
            ph[3] = *(const uint32_t*)&sh[SPH + pa + 8 * 72 + 8];
            pl[0] = *(const uint32_t*)&sh[SPL + pa];
            pl[1] = *(const uint32_t*)&sh[SPL + pa + 8 * 72];
            pl[2] = *(const uint32_t*)&sh[SPL + pa + 8];
            pl[3] = *(const uint32_t*)&sh[SPL + pa + 8 * 72 + 8];
#pragma unroll
            for (int nt = 0; nt < 8; nt++) {
                const int va = (nt * 8 + grp) * 72 + kc * 16 + tg * 2;
                uint32_t vh[2], vl[2];
                vh[0] = *(const uint32_t*)&sh[SVH + va];
                vh[1] = *(const uint32_t*)&sh[SVH + va + 8];
                vl[0] = *(const uint32_t*)&sh[SVL + va];
                vl[1] = *(const uint32_t*)&sh[SVL + va + 8];
                mma_f16(O[nt], ph, vh);
                mma_f16(O[nt], pl, vh);
                mma_f16(O[nt], ph, vl);
            }
        }
        __syncthreads();   // all reads of K/V SMEM done

        // Commit prefetched K/V for next tile
        if (pf) {
#pragma unroll
            for (int i = 0; i < 4; i++) {
                store_k(fk[i], kr[i]);
                store_v(fk[i], vr[i]);
            }
        }
        __syncthreads();   // next K/V visible
    }

    // ---- Normalize and write ctx ----
    const float inv0 = 1.0f / l0, inv1 = 1.0f / l1;
    const int r0 = q0 + wid * 16 + grp;
#pragma unroll
    for (int nt = 0; nt < 8; nt++) {
        const int c = h * HD + nt * 8 + tg * 2;
        *(float2*)&ctx[(size_t)r0 * EMB + c] =
            make_float2(O[nt][0] * inv0, O[nt][1] * inv0);
        *(float2*)&ctx[(size_t)(r0 + 8) * EMB + c] =
            make_float2(O[nt][2] * inv1, O[nt][3] * inv1);
    }
}

// ---------------------------------------------------------------------------
extern "C" void kernel_launch(void* const* d_in, const int* in_sizes, int n_in,
                              void* d_out, int out_size)
{
    (void)in_sizes; (void)n_in; (void)out_size;
    const float* x     = (const float*)d_in[0];   // [1,4096,768]
    const float* qkv_w = (const float*)d_in[1];   // [2304,768]
    const float* out_w = (const float*)d_in[2];   // [768,768]
    const float* out_b = (const float*)d_in[3];   // [768]
    float* out = (float*)d_out;                   // [1,4096,768]

    float *qkv = nullptr, *ctx = nullptr;
    cudaGetSymbolAddress((void**)&qkv, g_qkv);
    cudaGetSymbolAddress((void**)&ctx, g_ctx);

    // 1) QKV projection (HMMA bf16x3)
    const int smem3 = 6 * LT * (int)sizeof(__nv_bfloat16);
    cudaFuncSetAttribute(hmma_gemm_abt<3>,
                         cudaFuncAttributeMaxDynamicSharedMemorySize, smem3);
    hmma_gemm_abt<3><<<dim3(QKV_LD / 128, SEQ / 128), 256, smem3>>>(
        x, qkv_w, nullptr, qkv, SEQ, QKV_LD, EMB);

    // 2) HMMA flash attention
    cudaFuncSetAttribute(attn_hmma,
                         cudaFuncAttributeMaxDynamicSharedMemorySize, ATTN_SMEM_BYTES);
    attn_hmma<<<dim3(SEQ / 128, HEADS), 256, ATTN_SMEM_BYTES>>>(qkv, ctx);

    // 3) Output projection + bias (HMMA bf16x2)
    const int smem2 = 4 * LT * (int)sizeof(__nv_bfloat16);
    cudaFuncSetAttribute(hmma_gemm_abt<2>,
                         cudaFuncAttributeMaxDynamicSharedMemorySize, smem2);
    hmma_gemm_abt<2><<<dim3(EMB / 128, SEQ / 128), 256, smem2>>>(
        ctx, out_w, out_b, out, SEQ, EMB, EMB);
}

// round 9
// speedup vs baseline: 1.8573x; 1.0238x over previous
#include <cuda_runtime.h>
#include <cuda_bf16.h>
#include <cuda_fp16.h>
#include <math.h>
#include <stdint.h>

#define EMB 768
#define HEADS 12
#define HD 64
#define SEQ 4096
#define QKV_LD (3 * EMB)   // 2304

// Scratch (static device globals — no allocation)
__device__ __align__(16) float g_qkv[(size_t)SEQ * QKV_LD];  // [l][3*emb] : Q|K|V
__device__ __align__(16) float g_ctx[(size_t)SEQ * EMB];     // [l][h*64 + c]

// ---------------------------------------------------------------------------
// HMMA helpers (mma.sync — supported on base sm_103 target)
// ---------------------------------------------------------------------------
__device__ __forceinline__ void mma_bf16(float* d, const uint32_t* a, const uint32_t* b) {
    asm volatile(
        "mma.sync.aligned.m16n8k16.row.col.f32.bf16.bf16.f32 "
        "{%0,%1,%2,%3}, {%4,%5,%6,%7}, {%8,%9}, {%0,%1,%2,%3};"
        : "+f"(d[0]), "+f"(d[1]), "+f"(d[2]), "+f"(d[3])
        : "r"(a[0]), "r"(a[1]), "r"(a[2]), "r"(a[3]), "r"(b[0]), "r"(b[1]));
}
__device__ __forceinline__ void mma_f16(float* d, const uint32_t* a, const uint32_t* b) {
    asm volatile(
        "mma.sync.aligned.m16n8k16.row.col.f32.f16.f16.f32 "
        "{%0,%1,%2,%3}, {%4,%5,%6,%7}, {%8,%9}, {%0,%1,%2,%3};"
        : "+f"(d[0]), "+f"(d[1]), "+f"(d[2]), "+f"(d[3])
        : "r"(a[0]), "r"(a[1]), "r"(a[2]), "r"(a[3]), "r"(b[0]), "r"(b[1]));
}
__device__ __forceinline__ uint32_t h2bits(__half2 h) { return *(uint32_t*)&h; }

// fp32 pair -> fp16 hi/lo limbs (packed f16x2: x -> low half)
__device__ __forceinline__ void split_h2(float x, float y, uint32_t& hi, uint32_t& lo) {
    __half2 h = __floats2half2_rn(x, y);
    float2 f = __half22float2(h);
    __half2 l = __floats2half2_rn(x - f.x, y - f.y);
    hi = h2bits(h);
    lo = h2bits(l);
}

// fp32 pair -> bf16 limb split (for projection GEMMs)
__device__ __forceinline__ void split_pair_bf(
    float x, float y, uint32_t& h, uint32_t& m, uint32_t& l, bool want3)
{
    __nv_bfloat162 hb = __float22bfloat162_rn(make_float2(x, y));
    float2 hf = __bfloat1622float2(hb);
    float rx = x - hf.x, ry = y - hf.y;
    __nv_bfloat162 mb = __float22bfloat162_rn(make_float2(rx, ry));
    h = *(uint32_t*)&hb;
    m = *(uint32_t*)&mb;
    if (want3) {
        float2 mf = __bfloat1622float2(mb);
        __nv_bfloat162 lb = __float22bfloat162_rn(make_float2(rx - mf.x, ry - mf.y));
        l = *(uint32_t*)&lb;
    } else {
        l = 0;
    }
}

// ---------------------------------------------------------------------------
// HMMA GEMM: C[M,N] = A[M,K] @ B[N,K]^T (+bias), fp32 via bf16 limb split.
// __launch_bounds__(256, 2): 2 CTAs/SM (validated: tensor 52->62%).
// ---------------------------------------------------------------------------
#define LT (128 * 40)   // bf16 elements per limb tile

template<int NSPLIT>
__global__ __launch_bounds__(256, 2) void hmma_gemm_abt(
    const float* __restrict__ A, const float* __restrict__ B,
    const float* __restrict__ bias, float* __restrict__ C,
    int M, int N, int K)
{
    extern __shared__ __align__(16) char smem[];
    __nv_bfloat16* As = (__nv_bfloat16*)smem;
    __nv_bfloat16* Bs = As + NSPLIT * LT;

    const int tid  = threadIdx.x;
    const int lane = tid & 31;
    const int wid  = tid >> 5;
    const int wm   = wid >> 2;
    const int wn   = wid & 3;
    const int grp  = lane >> 2;
    const int tg   = lane & 3;
    const int bm0  = blockIdx.y * 128;
    const int bn0  = blockIdx.x * 128;

    float d[4][4][4];
#pragma unroll
    for (int am = 0; am < 4; am++)
#pragma unroll
        for (int an = 0; an < 4; an++)
#pragma unroll
            for (int r = 0; r < 4; r++) d[am][an][r] = 0.0f;

    const int NPR = (NSPLIT == 3) ? 6 : 3;
    const int PA[6] = {0, 0, 1, 0, 2, 1};
    const int PB[6] = {0, 1, 0, 2, 0, 1};

    for (int k0 = 0; k0 < K; k0 += 32) {
        __syncthreads();
#pragma unroll
        for (int half = 0; half < 2; half++) {
            const float* src = half ? (B + (size_t)bn0 * K) : (A + (size_t)bm0 * K);
            __nv_bfloat16* dst = half ? Bs : As;
#pragma unroll
            for (int it = 0; it < 2; it++) {
                const int f   = tid + it * 256;
                const int row = f >> 2;
                const int c8  = f & 3;
                const float* p = src + (size_t)row * K + k0 + c8 * 8;
                float4 v0 = *(const float4*)p;
                float4 v1 = *(const float4*)(p + 4);
                uint32_t h[4], m[4], l[4];
                split_pair_bf(v0.x, v0.y, h[0], m[0], l[0], NSPLIT == 3);
                split_pair_bf(v0.z, v0.w, h[1], m[1], l[1], NSPLIT == 3);
                split_pair_bf(v1.x, v1.y, h[2], m[2], l[2], NSPLIT == 3);
                split_pair_bf(v1.z, v1.w, h[3], m[3], l[3], NSPLIT == 3);
                const int base = row * 40 + c8 * 8;
#pragma unroll
                for (int j = 0; j < 4; j++) {
                    *(uint32_t*)&dst[0 * LT + base + j * 2] = h[j];
                    *(uint32_t*)&dst[1 * LT + base + j * 2] = m[j];
                    if (NSPLIT == 3)
                        *(uint32_t*)&dst[2 * LT + base + j * 2] = l[j];
                }
            }
        }
        __syncthreads();

#pragma unroll
        for (int ks = 0; ks < 2; ks++) {
#pragma unroll
            for (int p = 0; p < NPR; p++) {
                const int la = PA[p], lb = PB[p];
                uint32_t afr[4][4];
#pragma unroll
                for (int am = 0; am < 4; am++) {
                    const __nv_bfloat16* ap =
                        As + la * LT + (wm * 64 + am * 16 + grp) * 40 + ks * 16 + tg * 2;
                    afr[am][0] = *(const uint32_t*)ap;
                    afr[am][1] = *(const uint32_t*)(ap + 8 * 40);
                    afr[am][2] = *(const uint32_t*)(ap + 8);
                    afr[am][3] = *(const uint32_t*)(ap + 8 * 40 + 8);
                }
#pragma unroll
                for (int an = 0; an < 4; an++) {
                    const __nv_bfloat16* bp =
                        Bs + lb * LT + (wn * 32 + an * 8 + grp) * 40 + ks * 16 + tg * 2;
                    uint32_t bfr[2];
                    bfr[0] = *(const uint32_t*)bp;
                    bfr[1] = *(const uint32_t*)(bp + 8);
#pragma unroll
                    for (int am = 0; am < 4; am++)
                        mma_bf16(d[am][an], afr[am], bfr);
                }
            }
        }
    }

#pragma unroll
    for (int am = 0; am < 4; am++) {
        const int r0 = bm0 + wm * 64 + am * 16 + grp;
#pragma unroll
        for (int an = 0; an < 4; an++) {
            const int c0 = bn0 + wn * 32 + an * 8 + tg * 2;
            float bv0 = 0.0f, bv1 = 0.0f;
            if (bias) { bv0 = bias[c0]; bv1 = bias[c0 + 1]; }
            *(float2*)&C[(size_t)r0 * N + c0] =
                make_float2(d[am][an][0] + bv0, d[am][an][1] + bv1);
            *(float2*)&C[(size_t)(r0 + 8) * N + c0] =
                make_float2(d[am][an][2] + bv0, d[am][an][3] + bv1);
        }
    }
}

// ---------------------------------------------------------------------------
// HMMA flash attention, fp16 limb split, LAGGED-PV pipeline:
// iter i: S-MMA(i); rowmax/alpha; [PV(i-1) interleaved with exp(i)];
//         l-update; O*=alpha; P(i) store; commit K(i+1), V(i).
// K smem holds tile i while V smem holds tile i-1.
// ---------------------------------------------------------------------------
#define SQH 0                    // Q hi  [128][72]
#define SQL (SQH + 128 * 72)     // Q lo
#define SKH (SQL + 128 * 72)     // K hi  [64 key][72 d]
#define SKL (SKH + 64 * 72)      // K lo
#define SVH (SKL + 64 * 72)      // V^T hi [64 c][72 k]
#define SVL (SVH + 64 * 72)      // V^T lo
#define SPH (SVL + 64 * 72)      // P hi  [128 q][72 k]
#define SPL (SPH + 128 * 72)     // P lo
#define ATTN_HALVES (SPL + 128 * 72)          // 55296
#define ATTN_SMEM_BYTES (ATTN_HALVES * 2)     // 110592

__global__ __launch_bounds__(256, 2) void attn_hmma(
    const float* __restrict__ qkv, float* __restrict__ ctx)
{
    extern __shared__ __align__(16) __half sh[];
    const int tid  = threadIdx.x;
    const int lane = tid & 31;
    const int wid  = tid >> 5;
    const int grp  = lane >> 2;
    const int tg   = lane & 3;
    const int h    = blockIdx.y;
    const int q0   = blockIdx.x * 128;

    // Loader coords: 4 key fragments per thread, 4-d chunk.
    const int fk[4] = { tid >> 4, (tid + 256) >> 4, (tid + 512) >> 4, (tid + 768) >> 4 };
    const int fd = tid & 15;

    // ---- Load Q tile, scale by 8, split into fp16 limbs ----
#pragma unroll
    for (int f = tid; f < 512; f += 256) {
        const int row = f >> 2, ch = f & 3;
        const float* p = qkv + (size_t)(q0 + row) * QKV_LD + h * HD + ch * 16;
        uint32_t hi[8], lo[8];
#pragma unroll
        for (int j = 0; j < 4; j++) {
            float4 v = *(const float4*)(p + j * 4);
            split_h2(v.x * 8.0f, v.y * 8.0f, hi[j * 2], lo[j * 2]);
            split_h2(v.z * 8.0f, v.w * 8.0f, hi[j * 2 + 1], lo[j * 2 + 1]);
        }
        const int o = row * 72 + ch * 16;
        *(uint4*)&sh[SQH + o]     = make_uint4(hi[0], hi[1], hi[2], hi[3]);
        *(uint4*)&sh[SQH + o + 8] = make_uint4(hi[4], hi[5], hi[6], hi[7]);
        *(uint4*)&sh[SQL + o]     = make_uint4(lo[0], lo[1], lo[2], lo[3]);
        *(uint4*)&sh[SQL + o + 8] = make_uint4(lo[4], lo[5], lo[6], lo[7]);
    }

    // K store: [key][d] limbs (8-byte stores)
    auto store_k = [&](int key, float4 v) {
        uint32_t h0, l0_, h1, l1;
        split_h2(v.x, v.y, h0, l0_);
        split_h2(v.z, v.w, h1, l1);
        const int o = key * 72 + fd * 4;
        *(uint2*)&sh[SKH + o] = make_uint2(h0, h1);
        *(uint2*)&sh[SKL + o] = make_uint2(l0_, l1);
    };
    // V store transposed: [c][k] limbs (scalar half stores)
    auto store_v = [&](int key, float4 v) {
        float c4[4] = {v.x, v.y, v.z, v.w};
#pragma unroll
        for (int j = 0; j < 4; j++) {
            __half hh = __float2half_rn(c4[j]);
            sh[SVH + (fd * 4 + j) * 72 + key] = hh;
            sh[SVL + (fd * 4 + j) * 72 + key] = __float2half_rn(c4[j] - __half2float(hh));
        }
    };

    // ---- Preload K tile 0 only (V smem lags by one tile) ----
#pragma unroll
    for (int i = 0; i < 4; i++) {
        float4 kv = *(const float4*)(qkv + (size_t)fk[i] * QKV_LD + EMB + h * HD + fd * 4);
        store_k(fk[i], kv);
    }
    __syncthreads();

    float m0 = -1e30f, m1 = -1e30f, l0 = 0.0f, l1 = 0.0f;
    float O[8][4];
#pragma unroll
    for (int nt = 0; nt < 8; nt++)
#pragma unroll
        for (int r = 0; r < 4; r++) O[nt][r] = 0.0f;

    const int qrow = (wid * 16 + grp) * 72 + tg * 2;   // Q-row / P-row base

    for (int it = 0; it < SEQ / 64; it++) {
        const int kt = it * 64;
        const bool pfK = (it + 1) < SEQ / 64;

        // Prefetch K(it+1) and V(it) fp32 (latency hidden under S-MMA + PV)
        float4 kr[4], vr[4];
        if (pfK) {
#pragma unroll
            for (int i = 0; i < 4; i++)
                kr[i] = *(const float4*)(qkv + (size_t)(kt + 64 + fk[i]) * QKV_LD + EMB + h * HD + fd * 4);
        }
#pragma unroll
        for (int i = 0; i < 4; i++)
            vr[i] = *(const float4*)(qkv + (size_t)(kt + fk[i]) * QKV_LD + 2 * EMB + h * HD + fd * 4);

        // ---- S = Q K^T on tile it (3 fp16 limb products) ----
        float s[8][4];
#pragma unroll
        for (int nt = 0; nt < 8; nt++)
#pragma unroll
            for (int r = 0; r < 4; r++) s[nt][r] = 0.0f;

#pragma unroll
        for (int ks = 0; ks < 4; ks++) {
            const int qa = qrow + ks * 16;
            uint32_t ah[4], al_[4];
            ah[0] = *(const uint32_t*)&sh[SQH + qa];
            ah[1] = *(const uint32_t*)&sh[SQH + qa + 8 * 72];
            ah[2] = *(const uint32_t*)&sh[SQH + qa + 8];
            ah[3] = *(const uint32_t*)&sh[SQH + qa + 8 * 72 + 8];
            al_[0] = *(const uint32_t*)&sh[SQL + qa];
            al_[1] = *(const uint32_t*)&sh[SQL + qa + 8 * 72];
            al_[2] = *(const uint32_t*)&sh[SQL + qa + 8];
            al_[3] = *(const uint32_t*)&sh[SQL + qa + 8 * 72 + 8];
#pragma unroll
            for (int nt = 0; nt < 8; nt++) {
                const int ka = (nt * 8 + grp) * 72 + ks * 16 + tg * 2;
                uint32_t kh[2], kl[2];
                kh[0] = *(const uint32_t*)&sh[SKH + ka];
                kh[1] = *(const uint32_t*)&sh[SKH + ka + 8];
                kl[0] = *(const uint32_t*)&sh[SKL + ka];
                kl[1] = *(const uint32_t*)&sh[SKL + ka + 8];
                mma_f16(s[nt], ah, kh);
                mma_f16(s[nt], al_, kh);
                mma_f16(s[nt], ah, kl);
            }
        }

        // ---- rowmax + alpha ----
        float mx0 = -1e30f, mx1 = -1e30f;
#pragma unroll
        for (int nt = 0; nt < 8; nt++) {
            mx0 = fmaxf(mx0, fmaxf(s[nt][0], s[nt][1]));
            mx1 = fmaxf(mx1, fmaxf(s[nt][2], s[nt][3]));
        }
        mx0 = fmaxf(mx0, __shfl_xor_sync(0xffffffffu, mx0, 1));
        mx0 = fmaxf(mx0, __shfl_xor_sync(0xffffffffu, mx0, 2));
        mx1 = fmaxf(mx1, __shfl_xor_sync(0xffffffffu, mx1, 1));
        mx1 = fmaxf(mx1, __shfl_xor_sync(0xffffffffu, mx1, 2));

        const float mn0 = fmaxf(m0, mx0), mn1 = fmaxf(m1, mx1);
        const float al0 = __expf(m0 - mn0), al1 = __expf(m1 - mn1);
        m0 = mn0; m1 = mn1;

        float sum0 = 0.0f, sum1 = 0.0f;

        if (it > 0) {
            // ---- interleaved: PV(it-1) MMAs ‖ exp(it) ----
#pragma unroll
            for (int kc = 0; kc < 4; kc++) {
                const int pa = qrow + kc * 16;
                uint32_t ph[4], pl[4];
                ph[0] = *(const uint32_t*)&sh[SPH + pa];
                ph[1] = *(const uint32_t*)&sh[SPH + pa + 8 * 72];
                ph[2] = *(const uint32_t*)&sh[SPH + pa + 8];
                ph[3] = *(const uint32_t*)&sh[SPH + pa + 8 * 72 + 8];
                pl[0] = *(const uint32_t*)&sh[SPL + pa];
                pl[1] = *(const uint32_t*)&sh[SPL + pa + 8 * 72];
                pl[2] = *(const uint32_t*)&sh[SPL + pa + 8];
                pl[3] = *(const uint32_t*)&sh[SPL + pa + 8 * 72 + 8];
#pragma unroll
                for (int nt = 0; nt < 8; nt++) {
                    const int va = (nt * 8 + grp) * 72 + kc * 16 + tg * 2;
                    uint32_t vh[2], vl[2];
                    vh[0] = *(const uint32_t*)&sh[SVH + va];
                    vh[1] = *(const uint32_t*)&sh[SVH + va + 8];
                    vl[0] = *(const uint32_t*)&sh[SVL + va];
                    vl[1] = *(const uint32_t*)&sh[SVL + va + 8];
                    mma_f16(O[nt], ph, vh);
                    mma_f16(O[nt], pl, vh);
                    mma_f16(O[nt], ph, vl);
                    // interleave one row of exp per nt (independent of MMA regs)
                    if (nt < 2) {
                        const int e = kc * 2 + nt;
                        s[e][0] = __expf(s[e][0] - mn0); sum0 += s[e][0];
                        s[e][1] = __expf(s[e][1] - mn0); sum0 += s[e][1];
                        s[e][2] = __expf(s[e][2] - mn1); sum1 += s[e][2];
                        s[e][3] = __expf(s[e][3] - mn1); sum1 += s[e][3];
                    }
                }
            }
        } else {
#pragma unroll
            for (int nt = 0; nt < 8; nt++) {
                s[nt][0] = __expf(s[nt][0] - mn0); sum0 += s[nt][0];
                s[nt][1] = __expf(s[nt][1] - mn0); sum0 += s[nt][1];
                s[nt][2] = __expf(s[nt][2] - mn1); sum1 += s[nt][2];
                s[nt][3] = __expf(s[nt][3] - mn1); sum1 += s[nt][3];
            }
        }

        // ---- l update + O rescale (after PV(it-1) completed) ----
        sum0 += __shfl_xor_sync(0xffffffffu, sum0, 1);
        sum0 += __shfl_xor_sync(0xffffffffu, sum0, 2);
        sum1 += __shfl_xor_sync(0xffffffffu, sum1, 1);
        sum1 += __shfl_xor_sync(0xffffffffu, sum1, 2);
        l0 = l0 * al0 + sum0;
        l1 = l1 * al1 + sum1;

#pragma unroll
        for (int nt = 0; nt < 8; nt++) {
            O[nt][0] *= al0; O[nt][1] *= al0;
            O[nt][2] *= al1; O[nt][3] *= al1;
        }

        __syncwarp(0xffffffffu);   // PV reads of P(it-1) done before overwrite

        // ---- P(it) -> SMEM fp16 limbs (warp-private rows) ----
#pragma unroll
        for (int nt = 0; nt < 8; nt++) {
            uint32_t hh, ll;
            const int pa0 = qrow + nt * 8;
            split_h2(s[nt][0], s[nt][1], hh, ll);
            *(uint32_t*)&sh[SPH + pa0] = hh;
            *(uint32_t*)&sh[SPL + pa0] = ll;
            split_h2(s[nt][2], s[nt][3], hh, ll);
            *(uint32_t*)&sh[SPH + pa0 + 8 * 72] = hh;
            *(uint32_t*)&sh[SPL + pa0 + 8 * 72] = ll;
        }

        __syncthreads();   // all K(it)/V(it-1) smem reads done
        if (pfK) {
#pragma unroll
            for (int i = 0; i < 4; i++) store_k(fk[i], kr[i]);
        }
#pragma unroll
        for (int i = 0; i < 4; i++) store_v(fk[i], vr[i]);
        __syncthreads();   // K(it+1), V(it) visible
    }

    // ---- Epilogue: PV for the last tile ----
#pragma unroll
    for (int kc = 0; kc < 4; kc++) {
        const int pa = qrow + kc * 16;
        uint32_t ph[4], pl[4];
        ph[0] = *(const uint32_t*)&sh[SPH + pa];
        ph[1] = *(const uint32_t*)&sh[SPH + pa + 8 * 72];
        ph[2] = *(const uint32_t*)&sh[SPH + pa + 8];
        ph[3] = *(const uint32_t*)&sh[SPH + pa + 8 * 72 + 8];
        pl[0] = *(const uint32_t*)&sh[SPL + pa];
        pl[1] = *(const uint32_t*)&sh[SPL + pa + 8 * 72];
        pl[2] = *(const uint32_t*)&sh[SPL + pa + 8];
        pl[3] = *(const uint32_t*)&sh[SPL + pa + 8 * 72 + 8];
#pragma unroll
        for (int nt = 0; nt < 8; nt++) {
            const int va = (nt * 8 + grp) * 72 + kc * 16 + tg * 2;
            uint32_t vh[2], vl[2];
            vh[0] = *(const uint32_t*)&sh[SVH + va];
            vh[1] = *(const uint32_t*)&sh[SVH + va + 8];
            vl[0] = *(const uint32_t*)&sh[SVL + va];
            vl[1] = *(const uint32_t*)&sh[SVL + va + 8];
            mma_f16(O[nt], ph, vh);
            mma_f16(O[nt], pl, vh);
            mma_f16(O[nt], ph, vl);
        }
    }

    // ---- Normalize and write ctx ----
    const float inv0 = 1.0f / l0, inv1 = 1.0f / l1;
    const int r0 = q0 + wid * 16 + grp;
#pragma unroll
    for (int nt = 0; nt < 8; nt++) {
        const int c = h * HD + nt * 8 + tg * 2;
        *(float2*)&ctx[(size_t)r0 * EMB + c] =
            make_float2(O[nt][0] * inv0, O[nt][1] * inv0);
        *(float2*)&ctx[(size_t)(r0 + 8) * EMB + c] =
            make_float2(O[nt][2] * inv1, O[nt][3] * inv1);
    }
}

// ---------------------------------------------------------------------------
extern "C" void kernel_launch(void* const* d_in, const int* in_sizes, int n_in,
                              void* d_out, int out_size)
{
    (void)in_sizes; (void)n_in; (void)out_size;
    const float* x     = (const float*)d_in[0];   // [1,4096,768]
    const float* qkv_w = (const float*)d_in[1];   // [2304,768]
    const float* out_w = (const float*)d_in[2];   // [768,768]
    const float* out_b = (const float*)d_in[3];   // [768]
    float* out = (float*)d_out;                   // [1,4096,768]

    float *qkv = nullptr, *ctx = nullptr;
    cudaGetSymbolAddress((void**)&qkv, g_qkv);
    cudaGetSymbolAddress((void**)&ctx, g_ctx);

    // 1) QKV projection (HMMA bf16x3)
    const int smem3 = 6 * LT * (int)sizeof(__nv_bfloat16);
    cudaFuncSetAttribute(hmma_gemm_abt<3>,
                         cudaFuncAttributeMaxDynamicSharedMemorySize, smem3);
    hmma_gemm_abt<3><<<dim3(QKV_LD / 128, SEQ / 128), 256, smem3>>>(
        x, qkv_w, nullptr, qkv, SEQ, QKV_LD, EMB);

    // 2) HMMA flash attention (lagged-PV pipeline)
    cudaFuncSetAttribute(attn_hmma,
                         cudaFuncAttributeMaxDynamicSharedMemorySize, ATTN_SMEM_BYTES);
    attn_hmma<<<dim3(SEQ / 128, HEADS), 256, ATTN_SMEM_BYTES>>>(qkv, ctx);

    // 3) Output projection + bias (HMMA bf16x2)
    const int smem2 = 4 * LT * (int)sizeof(__nv_bfloat16);
    cudaFuncSetAttribute(hmma_gemm_abt<2>,
                         cudaFuncAttributeMaxDynamicSharedMemorySize, smem2);
    hmma_gemm_abt<2><<<dim3(EMB / 128, SEQ / 128), 256, smem2>>>(
        ctx, out_w, out_b, out, SEQ, EMB, EMB);
}

// round 10
// speedup vs baseline: 2.2403x; 1.2062x over previous
#include <cuda_runtime.h>
#include <cuda_bf16.h>
#include <cuda_fp16.h>
#include <math.h>
#include <stdint.h>

#define EMB 768
#define HEADS 12
#define HD 64
#define SEQ 4096
#define QKV_LD (3 * EMB)   // 2304
#define LIMB ((size_t)HEADS * SEQ * HD)   // halves per limb plane: 3145728

// Scratch (static device globals — no allocation)
__device__ __align__(16) float g_qkv[(size_t)SEQ * QKV_LD];  // [l][3*emb] : Q|K|V
__device__ __align__(16) float g_ctx[(size_t)SEQ * EMB];     // [l][h*64 + c]
__device__ __align__(16) __half g_k16[2 * HEADS * SEQ * HD]; // [limb][h][k][d]
__device__ __align__(16) __half g_v16[2 * HEADS * SEQ * HD]; // [limb][h][c][k]

// ---------------------------------------------------------------------------
// HMMA helpers (mma.sync — supported on base sm_103 target)
// ---------------------------------------------------------------------------
__device__ __forceinline__ void mma_bf16(float* d, const uint32_t* a, const uint32_t* b) {
    asm volatile(
        "mma.sync.aligned.m16n8k16.row.col.f32.bf16.bf16.f32 "
        "{%0,%1,%2,%3}, {%4,%5,%6,%7}, {%8,%9}, {%0,%1,%2,%3};"
        : "+f"(d[0]), "+f"(d[1]), "+f"(d[2]), "+f"(d[3])
        : "r"(a[0]), "r"(a[1]), "r"(a[2]), "r"(a[3]), "r"(b[0]), "r"(b[1]));
}
__device__ __forceinline__ void mma_f16(float* d, const uint32_t* a, const uint32_t* b) {
    asm volatile(
        "mma.sync.aligned.m16n8k16.row.col.f32.f16.f16.f32 "
        "{%0,%1,%2,%3}, {%4,%5,%6,%7}, {%8,%9}, {%0,%1,%2,%3};"
        : "+f"(d[0]), "+f"(d[1]), "+f"(d[2]), "+f"(d[3])
        : "r"(a[0]), "r"(a[1]), "r"(a[2]), "r"(a[3]), "r"(b[0]), "r"(b[1]));
}
__device__ __forceinline__ uint32_t h2bits(__half2 h) { return *(uint32_t*)&h; }

// fp32 pair -> fp16 hi/lo limbs (packed f16x2: x -> low half)
__device__ __forceinline__ void split_h2(float x, float y, uint32_t& hi, uint32_t& lo) {
    __half2 h = __floats2half2_rn(x, y);
    float2 f = __half22float2(h);
    __half2 l = __floats2half2_rn(x - f.x, y - f.y);
    hi = h2bits(h);
    lo = h2bits(l);
}

// fp32 pair -> bf16 limb split (for projection GEMMs)
__device__ __forceinline__ void split_pair_bf(
    float x, float y, uint32_t& h, uint32_t& m, uint32_t& l, bool want3)
{
    __nv_bfloat162 hb = __float22bfloat162_rn(make_float2(x, y));
    float2 hf = __bfloat1622float2(hb);
    float rx = x - hf.x, ry = y - hf.y;
    __nv_bfloat162 mb = __float22bfloat162_rn(make_float2(rx, ry));
    h = *(uint32_t*)&hb;
    m = *(uint32_t*)&mb;
    if (want3) {
        float2 mf = __bfloat1622float2(mb);
        __nv_bfloat162 lb = __float22bfloat162_rn(make_float2(rx - mf.x, ry - mf.y));
        l = *(uint32_t*)&lb;
    } else {
        l = 0;
    }
}

// ---------------------------------------------------------------------------
// HMMA GEMM: C[M,N] = A[M,K] @ B[N,K]^T (+bias), fp32 via bf16 limb split.
// (unchanged — passing; 2 CTAs/SM, tensor 62%)
// ---------------------------------------------------------------------------
#define LT (128 * 40)   // bf16 elements per limb tile

template<int NSPLIT>
__global__ __launch_bounds__(256, 2) void hmma_gemm_abt(
    const float* __restrict__ A, const float* __restrict__ B,
    const float* __restrict__ bias, float* __restrict__ C,
    int M, int N, int K)
{
    extern __shared__ __align__(16) char smem[];
    __nv_bfloat16* As = (__nv_bfloat16*)smem;
    __nv_bfloat16* Bs = As + NSPLIT * LT;

    const int tid  = threadIdx.x;
    const int lane = tid & 31;
    const int wid  = tid >> 5;
    const int wm   = wid >> 2;
    const int wn   = wid & 3;
    const int grp  = lane >> 2;
    const int tg   = lane & 3;
    const int bm0  = blockIdx.y * 128;
    const int bn0  = blockIdx.x * 128;

    float d[4][4][4];
#pragma unroll
    for (int am = 0; am < 4; am++)
#pragma unroll
        for (int an = 0; an < 4; an++)
#pragma unroll
            for (int r = 0; r < 4; r++) d[am][an][r] = 0.0f;

    const int NPR = (NSPLIT == 3) ? 6 : 3;
    const int PA[6] = {0, 0, 1, 0, 2, 1};
    const int PB[6] = {0, 1, 0, 2, 0, 1};

    for (int k0 = 0; k0 < K; k0 += 32) {
        __syncthreads();
#pragma unroll
        for (int half = 0; half < 2; half++) {
            const float* src = half ? (B + (size_t)bn0 * K) : (A + (size_t)bm0 * K);
            __nv_bfloat16* dst = half ? Bs : As;
#pragma unroll
            for (int it = 0; it < 2; it++) {
                const int f   = tid + it * 256;
                const int row = f >> 2;
                const int c8  = f & 3;
                const float* p = src + (size_t)row * K + k0 + c8 * 8;
                float4 v0 = *(const float4*)p;
                float4 v1 = *(const float4*)(p + 4);
                uint32_t h[4], m[4], l[4];
                split_pair_bf(v0.x, v0.y, h[0], m[0], l[0], NSPLIT == 3);
                split_pair_bf(v0.z, v0.w, h[1], m[1], l[1], NSPLIT == 3);
                split_pair_bf(v1.x, v1.y, h[2], m[2], l[2], NSPLIT == 3);
                split_pair_bf(v1.z, v1.w, h[3], m[3], l[3], NSPLIT == 3);
                const int base = row * 40 + c8 * 8;
#pragma unroll
                for (int j = 0; j < 4; j++) {
                    *(uint32_t*)&dst[0 * LT + base + j * 2] = h[j];
                    *(uint32_t*)&dst[1 * LT + base + j * 2] = m[j];
                    if (NSPLIT == 3)
                        *(uint32_t*)&dst[2 * LT + base + j * 2] = l[j];
                }
            }
        }
        __syncthreads();

#pragma unroll
        for (int ks = 0; ks < 2; ks++) {
#pragma unroll
            for (int p = 0; p < NPR; p++) {
                const int la = PA[p], lb = PB[p];
                uint32_t afr[4][4];
#pragma unroll
                for (int am = 0; am < 4; am++) {
                    const __nv_bfloat16* ap =
                        As + la * LT + (wm * 64 + am * 16 + grp) * 40 + ks * 16 + tg * 2;
                    afr[am][0] = *(const uint32_t*)ap;
                    afr[am][1] = *(const uint32_t*)(ap + 8 * 40);
                    afr[am][2] = *(const uint32_t*)(ap + 8);
                    afr[am][3] = *(const uint32_t*)(ap + 8 * 40 + 8);
                }
#pragma unroll
                for (int an = 0; an < 4; an++) {
                    const __nv_bfloat16* bp =
                        Bs + lb * LT + (wn * 32 + an * 8 + grp) * 40 + ks * 16 + tg * 2;
                    uint32_t bfr[2];
                    bfr[0] = *(const uint32_t*)bp;
                    bfr[1] = *(const uint32_t*)(bp + 8);
#pragma unroll
                    for (int am = 0; am < 4; am++)
                        mma_bf16(d[am][an], afr[am], bfr);
                }
            }
        }
    }

#pragma unroll
    for (int am = 0; am < 4; am++) {
        const int r0 = bm0 + wm * 64 + am * 16 + grp;
#pragma unroll
        for (int an = 0; an < 4; an++) {
            const int c0 = bn0 + wn * 32 + an * 8 + tg * 2;
            float bv0 = 0.0f, bv1 = 0.0f;
            if (bias) { bv0 = bias[c0]; bv1 = bias[c0 + 1]; }
            *(float2*)&C[(size_t)r0 * N + c0] =
                make_float2(d[am][an][0] + bv0, d[am][an][1] + bv1);
            *(float2*)&C[(size_t)(r0 + 8) * N + c0] =
                make_float2(d[am][an][2] + bv0, d[am][an][3] + bv1);
        }
    }
}

// ---------------------------------------------------------------------------
// Prep: split K (fp32) into fp16 hi/lo limbs, layout [limb][h][k][d].
// grid 768 x 256; unit = one (h, k, 16-d chunk).
// ---------------------------------------------------------------------------
__global__ __launch_bounds__(256) void prep_k(
    const float* __restrict__ qkv, __half* __restrict__ k16)
{
    const int u  = blockIdx.x * 256 + threadIdx.x;   // 0..196607
    const int hk = u >> 2, ch = u & 3;
    const int h = hk >> 12, k = hk & 4095;
    const float* src = qkv + (size_t)k * QKV_LD + EMB + h * HD + ch * 16;
    __half* dh = k16 + ((size_t)h * SEQ + k) * HD + ch * 16;

    uint32_t hi[8], lo[8];
#pragma unroll
    for (int j = 0; j < 4; j++) {
        float4 v = *(const float4*)(src + j * 4);
        split_h2(v.x, v.y, hi[j * 2], lo[j * 2]);
        split_h2(v.z, v.w, hi[j * 2 + 1], lo[j * 2 + 1]);
    }
    *(uint4*)dh       = make_uint4(hi[0], hi[1], hi[2], hi[3]);
    *(uint4*)(dh + 8) = make_uint4(hi[4], hi[5], hi[6], hi[7]);
    __half* dl = dh + LIMB;
    *(uint4*)dl       = make_uint4(lo[0], lo[1], lo[2], lo[3]);
    *(uint4*)(dl + 8) = make_uint4(lo[4], lo[5], lo[6], lo[7]);
}

// ---------------------------------------------------------------------------
// Prep: split V and transpose to [limb][h][c][k]. grid (64 kblocks, 12 h).
// FIXED from round 6: phase-2 now copies the FULL 16-half quarter row
// (two uint4 per limb) instead of striding past half the data.
// ---------------------------------------------------------------------------
__global__ __launch_bounds__(256) void prep_v(
    const float* __restrict__ qkv, __half* __restrict__ v16)
{
    __shared__ __align__(16) __half sv[2][64][80];   // stride 80: 16B-aligned rows
    const int h  = blockIdx.y, kb = blockIdx.x;
    const int t  = threadIdx.x;
    {
        const int k = t >> 2, ch = t & 3;
        const float* src = qkv + (size_t)(kb * 64 + k) * QKV_LD + 2 * EMB + h * HD + ch * 16;
#pragma unroll
        for (int j = 0; j < 16; j += 2) {
            float2 v = *(const float2*)(src + j);
            __half2 a = __floats2half2_rn(v.x, v.y);
            float2 f = __half22float2(a);
            __half2 r = __floats2half2_rn(v.x - f.x, v.y - f.y);
            const int c = ch * 16 + j;
            sv[0][c][k]     = __low2half(a);
            sv[0][c + 1][k] = __high2half(a);
            sv[1][c][k]     = __low2half(r);
            sv[1][c + 1][k] = __high2half(r);
        }
    }
    __syncthreads();
    {
        const int c = t >> 2, kc = t & 3;
        __half* dst = v16 + ((size_t)h * HD + c) * SEQ + kb * 64 + kc * 16;
#pragma unroll
        for (int j = 0; j < 2; j++) {
            *(uint4*)(dst + j * 8)        = *(const uint4*)&sv[0][c][kc * 16 + j * 8];
            *(uint4*)(dst + LIMB + j * 8) = *(const uint4*)&sv[1][c][kc * 16 + j * 8];
        }
    }
}

// ---------------------------------------------------------------------------
// HMMA flash attention, fp16 limb split, lagged-PV pipeline, prep'd K/V:
// K/V arrive as fp16 limbs in global; tile fill is pure uint4 LDG + uint2 STS.
// ---------------------------------------------------------------------------
#define SQH 0                    // Q hi  [128][72]
#define SQL (SQH + 128 * 72)     // Q lo
#define SKH (SQL + 128 * 72)     // K hi  [64 key][72 d]
#define SKL (SKH + 64 * 72)      // K lo
#define SVH (SKL + 64 * 72)      // V^T hi [64 c][72 k]
#define SVL (SVH + 64 * 72)      // V^T lo
#define SPH (SVL + 64 * 72)      // P hi  [128 q][72 k]
#define SPL (SPH + 128 * 72)     // P lo
#define ATTN_HALVES (SPL + 128 * 72)          // 55296
#define ATTN_SMEM_BYTES (ATTN_HALVES * 2)     // 110592

__global__ __launch_bounds__(256, 2) void attn_hmma(
    const float* __restrict__ qkv,
    const __half* __restrict__ k16, const __half* __restrict__ v16,
    float* __restrict__ ctx)
{
    extern __shared__ __align__(16) __half sh[];
    const int tid  = threadIdx.x;
    const int lane = tid & 31;
    const int wid  = tid >> 5;
    const int grp  = lane >> 2;
    const int tg   = lane & 3;
    const int h    = blockIdx.y;
    const int q0   = blockIdx.x * 128;

    // ---- Load Q tile, scale by 8, split into fp16 limbs (once) ----
#pragma unroll
    for (int f = tid; f < 512; f += 256) {
        const int row = f >> 2, ch = f & 3;
        const float* p = qkv + (size_t)(q0 + row) * QKV_LD + h * HD + ch * 16;
        uint32_t hi[8], lo[8];
#pragma unroll
        for (int j = 0; j < 4; j++) {
            float4 v = *(const float4*)(p + j * 4);
            split_h2(v.x * 8.0f, v.y * 8.0f, hi[j * 2], lo[j * 2]);
            split_h2(v.z * 8.0f, v.w * 8.0f, hi[j * 2 + 1], lo[j * 2 + 1]);
        }
        const int o = row * 72 + ch * 16;
        *(uint4*)&sh[SQH + o]     = make_uint4(hi[0], hi[1], hi[2], hi[3]);
        *(uint4*)&sh[SQH + o + 8] = make_uint4(hi[4], hi[5], hi[6], hi[7]);
        *(uint4*)&sh[SQL + o]     = make_uint4(lo[0], lo[1], lo[2], lo[3]);
        *(uint4*)&sh[SQL + o + 8] = make_uint4(lo[4], lo[5], lo[6], lo[7]);
    }

    const __half* kP = k16 + (size_t)h * SEQ * HD;
    const __half* vP = v16 + (size_t)h * HD * SEQ;

    // Chunk decode: g = tid + i*256 -> (limb, row, 8-half segment)
    int clt[4], crow[4], cseg[4];
#pragma unroll
    for (int i = 0; i < 4; i++) {
        const int g = tid + i * 256;
        clt[i]  = g >> 9;
        crow[i] = (g >> 3) & 63;
        cseg[i] = g & 7;
    }

    auto sts_chunk = [&](int base_h, int base_l, int i, uint4 v) {
        const int off = (base_h + (clt[i] ? (base_l - base_h) : 0))
                        + crow[i] * 72 + cseg[i] * 8;
        *(uint2*)&sh[off]     = make_uint2(v.x, v.y);
        *(uint2*)&sh[off + 4] = make_uint2(v.z, v.w);
    };

    // ---- Preload K(0) ----
    {
        uint4 kc4[4];
#pragma unroll
        for (int i = 0; i < 4; i++)
            kc4[i] = *(const uint4*)(kP + clt[i] * LIMB + (size_t)crow[i] * HD + cseg[i] * 8);
#pragma unroll
        for (int i = 0; i < 4; i++) sts_chunk(SKH, SKL, i, kc4[i]);
    }
    __syncthreads();

    float m0 = -1e30f, m1 = -1e30f, l0 = 0.0f, l1 = 0.0f;
    float O[8][4];
#pragma unroll
    for (int nt = 0; nt < 8; nt++)
#pragma unroll
        for (int r = 0; r < 4; r++) O[nt][r] = 0.0f;

    const int qrow = (wid * 16 + grp) * 72 + tg * 2;   // Q-row / P-row base

    for (int it = 0; it < SEQ / 64; it++) {
        const int kt = it * 64;
        const bool pfK = (it + 1) < SEQ / 64;

        // Prefetch K(it+1) and V(it) limb chunks (hidden under S-MMA + PV)
        uint4 kc4[4], vc4[4];
        if (pfK) {
#pragma unroll
            for (int i = 0; i < 4; i++)
                kc4[i] = *(const uint4*)(kP + clt[i] * LIMB
                             + (size_t)(kt + 64 + crow[i]) * HD + cseg[i] * 8);
        }
#pragma unroll
        for (int i = 0; i < 4; i++)
            vc4[i] = *(const uint4*)(vP + clt[i] * LIMB
                         + (size_t)crow[i] * SEQ + kt + cseg[i] * 8);

        // ---- S = Q K^T on tile it (3 fp16 limb products) ----
        float s[8][4];
#pragma unroll
        for (int nt = 0; nt < 8; nt++)
#pragma unroll
            for (int r = 0; r < 4; r++) s[nt][r] = 0.0f;

#pragma unroll
        for (int ks = 0; ks < 4; ks++) {
            const int qa = qrow + ks * 16;
            uint32_t ah[4], al_[4];
            ah[0] = *(const uint32_t*)&sh[SQH + qa];
            ah[1] = *(const uint32_t*)&sh[SQH + qa + 8 * 72];
            ah[2] = *(const uint32_t*)&sh[SQH + qa + 8];
            ah[3] = *(const uint32_t*)&sh[SQH + qa + 8 * 72 + 8];
            al_[0] = *(const uint32_t*)&sh[SQL + qa];
            al_[1] = *(const uint32_t*)&sh[SQL + qa + 8 * 72];
            al_[2] = *(const uint32_t*)&sh[SQL + qa + 8];
            al_[3] = *(const uint32_t*)&sh[SQL + qa + 8 * 72 + 8];
#pragma unroll
            for (int nt = 0; nt < 8; nt++) {
                const int ka = (nt * 8 + grp) * 72 + ks * 16 + tg * 2;
                uint32_t kh[2], kl[2];
                kh[0] = *(const uint32_t*)&sh[SKH + ka];
                kh[1] = *(const uint32_t*)&sh[SKH + ka + 8];
                kl[0] = *(const uint32_t*)&sh[SKL + ka];
                kl[1] = *(const uint32_t*)&sh[SKL + ka + 8];
                mma_f16(s[nt], ah, kh);
                mma_f16(s[nt], al_, kh);
                mma_f16(s[nt], ah, kl);
            }
        }

        // ---- rowmax + alpha ----
        float mx0 = -1e30f, mx1 = -1e30f;
#pragma unroll
        for (int nt = 0; nt < 8; nt++) {
            mx0 = fmaxf(mx0, fmaxf(s[nt][0], s[nt][1]));
            mx1 = fmaxf(mx1, fmaxf(s[nt][2], s[nt][3]));
        }
        mx0 = fmaxf(mx0, __shfl_xor_sync(0xffffffffu, mx0, 1));
        mx0 = fmaxf(mx0, __shfl_xor_sync(0xffffffffu, mx0, 2));
        mx1 = fmaxf(mx1, __shfl_xor_sync(0xffffffffu, mx1, 1));
        mx1 = fmaxf(mx1, __shfl_xor_sync(0xffffffffu, mx1, 2));

        const float mn0 = fmaxf(m0, mx0), mn1 = fmaxf(m1, mx1);
        const float al0 = __expf(m0 - mn0), al1 = __expf(m1 - mn1);
        m0 = mn0; m1 = mn1;

        float sum0 = 0.0f, sum1 = 0.0f;

        if (it > 0) {
            // ---- interleaved: PV(it-1) MMAs ‖ exp(it) ----
#pragma unroll
            for (int kc = 0; kc < 4; kc++) {
                const int pa = qrow + kc * 16;
                uint32_t ph[4], pl[4];
                ph[0] = *(const uint32_t*)&sh[SPH + pa];
                ph[1] = *(const uint32_t*)&sh[SPH + pa + 8 * 72];
                ph[2] = *(const uint32_t*)&sh[SPH + pa + 8];
                ph[3] = *(const uint32_t*)&sh[SPH + pa + 8 * 72 + 8];
                pl[0] = *(const uint32_t*)&sh[SPL + pa];
                pl[1] = *(const uint32_t*)&sh[SPL + pa + 8 * 72];
                pl[2] = *(const uint32_t*)&sh[SPL + pa + 8];
                pl[3] = *(const uint32_t*)&sh[SPL + pa + 8 * 72 + 8];
#pragma unroll
                for (int nt = 0; nt < 8; nt++) {
                    const int va = (nt * 8 + grp) * 72 + kc * 16 + tg * 2;
                    uint32_t vh[2], vl[2];
                    vh[0] = *(const uint32_t*)&sh[SVH + va];
                    vh[1] = *(const uint32_t*)&sh[SVH + va + 8];
                    vl[0] = *(const uint32_t*)&sh[SVL + va];
                    vl[1] = *(const uint32_t*)&sh[SVL + va + 8];
                    mma_f16(O[nt], ph, vh);
                    mma_f16(O[nt], pl, vh);
                    mma_f16(O[nt], ph, vl);
                    if (nt < 2) {
                        const int e = kc * 2 + nt;
                        s[e][0] = __expf(s[e][0] - mn0); sum0 += s[e][0];
                        s[e][1] = __expf(s[e][1] - mn0); sum0 += s[e][1];
                        s[e][2] = __expf(s[e][2] - mn1); sum1 += s[e][2];
                        s[e][3] = __expf(s[e][3] - mn1); sum1 += s[e][3];
                    }
                }
            }
        } else {
#pragma unroll
            for (int nt = 0; nt < 8; nt++) {
                s[nt][0] = __expf(s[nt][0] - mn0); sum0 += s[nt][0];
                s[nt][1] = __expf(s[nt][1] - mn0); sum0 += s[nt][1];
                s[nt][2] = __expf(s[nt][2] - mn1); sum1 += s[nt][2];
                s[nt][3] = __expf(s[nt][3] - mn1); sum1 += s[nt][3];
            }
        }

        // ---- l update + O rescale (after PV(it-1) completed) ----
        sum0 += __shfl_xor_sync(0xffffffffu, sum0, 1);
        sum0 += __shfl_xor_sync(0xffffffffu, sum0, 2);
        sum1 += __shfl_xor_sync(0xffffffffu, sum1, 1);
        sum1 += __shfl_xor_sync(0xffffffffu, sum1, 2);
        l0 = l0 * al0 + sum0;
        l1 = l1 * al1 + sum1;

#pragma unroll
        for (int nt = 0; nt < 8; nt++) {
            O[nt][0] *= al0; O[nt][1] *= al0;
            O[nt][2] *= al1; O[nt][3] *= al1;
        }

        __syncwarp(0xffffffffu);   // PV reads of P(it-1) done before overwrite

        // ---- P(it) -> SMEM fp16 limbs (warp-private rows) ----
#pragma unroll
        for (int nt = 0; nt < 8; nt++) {
            uint32_t hh, ll;
            const int pa0 = qrow + nt * 8;
            split_h2(s[nt][0], s[nt][1], hh, ll);
            *(uint32_t*)&sh[SPH + pa0] = hh;
            *(uint32_t*)&sh[SPL + pa0] = ll;
            split_h2(s[nt][2], s[nt][3], hh, ll);
            *(uint32_t*)&sh[SPH + pa0 + 8 * 72] = hh;
            *(uint32_t*)&sh[SPL + pa0 + 8 * 72] = ll;
        }

        __syncthreads();   // all K(it)/V(it-1) smem reads done
        if (pfK) {
#pragma unroll
            for (int i = 0; i < 4; i++) sts_chunk(SKH, SKL, i, kc4[i]);
        }
#pragma unroll
        for (int i = 0; i < 4; i++) sts_chunk(SVH, SVL, i, vc4[i]);
        __syncthreads();   // K(it+1), V(it) visible
    }

    // ---- Epilogue: PV for the last tile ----
#pragma unroll
    for (int kc = 0; kc < 4; kc++) {
        const int pa = qrow + kc * 16;
        uint32_t ph[4], pl[4];
        ph[0] = *(const uint32_t*)&sh[SPH + pa];
        ph[1] = *(const uint32_t*)&sh[SPH + pa + 8 * 72];
        ph[2] = *(const uint32_t*)&sh[SPH + pa + 8];
        ph[3] = *(const uint32_t*)&sh[SPH + pa + 8 * 72 + 8];
        pl[0] = *(const uint32_t*)&sh[SPL + pa];
        pl[1] = *(const uint32_t*)&sh[SPL + pa + 8 * 72];
        pl[2] = *(const uint32_t*)&sh[SPL + pa + 8];
        pl[3] = *(const uint32_t*)&sh[SPL + pa + 8 * 72 + 8];
#pragma unroll
        for (int nt = 0; nt < 8; nt++) {
            const int va = (nt * 8 + grp) * 72 + kc * 16 + tg * 2;
            uint32_t vh[2], vl[2];
            vh[0] = *(const uint32_t*)&sh[SVH + va];
            vh[1] = *(const uint32_t*)&sh[SVH + va + 8];
            vl[0] = *(const uint32_t*)&sh[SVL + va];
            vl[1] = *(const uint32_t*)&sh[SVL + va + 8];
            mma_f16(O[nt], ph, vh);
            mma_f16(O[nt], pl, vh);
            mma_f16(O[nt], ph, vl);
        }
    }

    // ---- Normalize and write ctx ----
    const float inv0 = 1.0f / l0, inv1 = 1.0f / l1;
    const int r0 = q0 + wid * 16 + grp;
#pragma unroll
    for (int nt = 0; nt < 8; nt++) {
        const int c = h * HD + nt * 8 + tg * 2;
        *(float2*)&ctx[(size_t)r0 * EMB + c] =
            make_float2(O[nt][0] * inv0, O[nt][1] * inv0);
        *(float2*)&ctx[(size_t)(r0 + 8) * EMB + c] =
            make_float2(O[nt][2] * inv1, O[nt][3] * inv1);
    }
}

// ---------------------------------------------------------------------------
extern "C" void kernel_launch(void* const* d_in, const int* in_sizes, int n_in,
                              void* d_out, int out_size)
{
    (void)in_sizes; (void)n_in; (void)out_size;
    const float* x     = (const float*)d_in[0];   // [1,4096,768]
    const float* qkv_w = (const float*)d_in[1];   // [2304,768]
    const float* out_w = (const float*)d_in[2];   // [768,768]
    const float* out_b = (const float*)d_in[3];   // [768]
    float* out = (float*)d_out;                   // [1,4096,768]

    float *qkv = nullptr, *ctx = nullptr;
    __half *k16 = nullptr, *v16 = nullptr;
    cudaGetSymbolAddress((void**)&qkv, g_qkv);
    cudaGetSymbolAddress((void**)&ctx, g_ctx);
    cudaGetSymbolAddress((void**)&k16, g_k16);
    cudaGetSymbolAddress((void**)&v16, g_v16);

    // 1) QKV projection (HMMA bf16x3)
    const int smem3 = 6 * LT * (int)sizeof(__nv_bfloat16);
    cudaFuncSetAttribute(hmma_gemm_abt<3>,
                         cudaFuncAttributeMaxDynamicSharedMemorySize, smem3);
    hmma_gemm_abt<3><<<dim3(QKV_LD / 128, SEQ / 128), 256, smem3>>>(
        x, qkv_w, nullptr, qkv, SEQ, QKV_LD, EMB);

    // 2) K/V fp16 limb pre-split (once, instead of per q-tile)
    prep_k<<<768, 256>>>(qkv, k16);
    prep_v<<<dim3(64, HEADS), 256>>>(qkv, v16);

    // 3) HMMA flash attention (lagged-PV pipeline, prep'd K/V)
    cudaFuncSetAttribute(attn_hmma,
                         cudaFuncAttributeMaxDynamicSharedMemorySize, ATTN_SMEM_BYTES);
    attn_hmma<<<dim3(SEQ / 128, HEADS), 256, ATTN_SMEM_BYTES>>>(qkv, k16, v16, ctx);

    // 4) Output projection + bias (HMMA bf16x2)
    const int smem2 = 4 * LT * (int)sizeof(__nv_bfloat16);
    cudaFuncSetAttribute(hmma_gemm_abt<2>,
                         cudaFuncAttributeMaxDynamicSharedMemorySize, smem2);
    hmma_gemm_abt<2><<<dim3(EMB / 128, SEQ / 128), 256, smem2>>>(
        ctx, out_w, out_b, out, SEQ, EMB, EMB);
}